// round 2
// baseline (speedup 1.0000x reference)
#include <cuda_runtime.h>
#include <math.h>

#define NN    1025
#define CC    768
#define HH    12
#define HD    64
#define BH    96        // B*H = 8*12
#define MROWS 8200      // B*N

// ---------------- scratch (device globals: no allocation allowed) ----------
__device__ float g_q[BH * NN * HD];      // 25.2 MB, pre-scaled by 1/8
__device__ float g_k[BH * NN * HD];
__device__ float g_v[BH * NN * HD];
__device__ float g_ao[MROWS * CC];       // attention output, [B,N,C]
__device__ unsigned char g_bucket[NN * NN];

// ---------------- bucket table (static geometry, fp64 to match numpy) ------
__global__ void bucket_kernel() {
    int idx = blockIdx.x * 256 + threadIdx.x;
    if (idx >= NN * NN) return;
    int i = idx / NN, j = idx - (idx / NN) * NN;
    int v;
    if (i == 0 || j == 0) {
        v = 7;  // cls-token bucket
    } else {
        int p = i - 1, q = j - 1;
        int dy = (p >> 5) - (q >> 5);
        int dx = (p & 31) - (q & 31);
        double dis = rint(sqrt((double)(dy * dy + dx * dx)));
        if (dis <= 1.9) {
            v = (int)dis;
        } else {
            double t = rint(1.9 + log(dis / 1.9) / log(8.0) * 1.9);
            if (t > 3.8) t = 3.8;
            v = (int)t;   // truncation matches np .astype(int64) after minimum
        }
    }
    g_bucket[idx] = (unsigned char)v;
}

// ---------------- QKV GEMM: C[m][n] = sum_k X[m][k]*W[n][k] ----------------
// 128x128 tile, BK=16, 256 threads, 8x8 microtile. Epilogue scatters into
// q (scaled by 0.125) / k / v with [bh][n][d] layout.
__global__ __launch_bounds__(256) void qkv_gemm(const float* __restrict__ X,
                                                const float* __restrict__ W) {
    __shared__ float Ast[16][132];
    __shared__ float Bst[16][132];
    int tid = threadIdx.x;
    int ty = tid >> 4, tx = tid & 15;
    int m0 = blockIdx.y * 128, n0 = blockIdx.x * 128;

    float acc[8][8];
#pragma unroll
    for (int a = 0; a < 8; a++)
#pragma unroll
        for (int b = 0; b < 8; b++) acc[a][b] = 0.f;

    int lrow = tid >> 2;          // 0..63
    int lk4  = (tid & 3) * 4;     // 0,4,8,12

    for (int k0 = 0; k0 < CC; k0 += 16) {
#pragma unroll
        for (int p = 0; p < 2; p++) {
            int row = lrow + p * 64;
            float4 av = make_float4(0.f, 0.f, 0.f, 0.f);
            int gm = m0 + row;
            if (gm < MROWS) av = *(const float4*)(X + (size_t)gm * CC + k0 + lk4);
            Ast[lk4 + 0][row] = av.x; Ast[lk4 + 1][row] = av.y;
            Ast[lk4 + 2][row] = av.z; Ast[lk4 + 3][row] = av.w;
            float4 bv = *(const float4*)(W + (size_t)(n0 + row) * CC + k0 + lk4);
            Bst[lk4 + 0][row] = bv.x; Bst[lk4 + 1][row] = bv.y;
            Bst[lk4 + 2][row] = bv.z; Bst[lk4 + 3][row] = bv.w;
        }
        __syncthreads();
#pragma unroll
        for (int kk = 0; kk < 16; kk++) {
            float a[8], b[8];
            *(float4*)&a[0] = *(float4*)&Ast[kk][ty * 8];
            *(float4*)&a[4] = *(float4*)&Ast[kk][ty * 8 + 4];
            *(float4*)&b[0] = *(float4*)&Bst[kk][tx * 8];
            *(float4*)&b[4] = *(float4*)&Bst[kk][tx * 8 + 4];
#pragma unroll
            for (int ii = 0; ii < 8; ii++)
#pragma unroll
                for (int jj = 0; jj < 8; jj++)
                    acc[ii][jj] = fmaf(a[ii], b[jj], acc[ii][jj]);
        }
        __syncthreads();
    }

#pragma unroll
    for (int ii = 0; ii < 8; ii++) {
        int gm = m0 + ty * 8 + ii;
        if (gm >= MROWS) continue;
        int b = gm / NN, i = gm - b * NN;
#pragma unroll
        for (int jj = 0; jj < 8; jj++) {
            int ng = n0 + tx * 8 + jj;
            int which = ng / CC;
            int cc = ng - which * CC;
            int h = cc >> 6, d = cc & 63;
            int idx = ((b * HH + h) * NN + i) * HD + d;
            float v = acc[ii][jj];
            if (which == 0)      g_q[idx] = v * 0.125f;   // scale = hd^-0.5
            else if (which == 1) g_k[idx] = v;
            else                 g_v[idx] = v;
        }
    }
}

// ---------------- proj GEMM: out[m][n] = sum_k AO[m][k]*W[n][k] + bias[n] ---
__global__ __launch_bounds__(256) void proj_gemm(const float* __restrict__ W,
                                                 const float* __restrict__ bias,
                                                 float* __restrict__ out) {
    __shared__ float Ast[16][132];
    __shared__ float Bst[16][132];
    int tid = threadIdx.x;
    int ty = tid >> 4, tx = tid & 15;
    int m0 = blockIdx.y * 128, n0 = blockIdx.x * 128;

    float acc[8][8];
#pragma unroll
    for (int a = 0; a < 8; a++)
#pragma unroll
        for (int b = 0; b < 8; b++) acc[a][b] = 0.f;

    int lrow = tid >> 2;
    int lk4  = (tid & 3) * 4;

    for (int k0 = 0; k0 < CC; k0 += 16) {
#pragma unroll
        for (int p = 0; p < 2; p++) {
            int row = lrow + p * 64;
            float4 av = make_float4(0.f, 0.f, 0.f, 0.f);
            int gm = m0 + row;
            if (gm < MROWS) av = *(const float4*)(g_ao + (size_t)gm * CC + k0 + lk4);
            Ast[lk4 + 0][row] = av.x; Ast[lk4 + 1][row] = av.y;
            Ast[lk4 + 2][row] = av.z; Ast[lk4 + 3][row] = av.w;
            float4 bv = *(const float4*)(W + (size_t)(n0 + row) * CC + k0 + lk4);
            Bst[lk4 + 0][row] = bv.x; Bst[lk4 + 1][row] = bv.y;
            Bst[lk4 + 2][row] = bv.z; Bst[lk4 + 3][row] = bv.w;
        }
        __syncthreads();
#pragma unroll
        for (int kk = 0; kk < 16; kk++) {
            float a[8], b[8];
            *(float4*)&a[0] = *(float4*)&Ast[kk][ty * 8];
            *(float4*)&a[4] = *(float4*)&Ast[kk][ty * 8 + 4];
            *(float4*)&b[0] = *(float4*)&Bst[kk][tx * 8];
            *(float4*)&b[4] = *(float4*)&Bst[kk][tx * 8 + 4];
#pragma unroll
            for (int ii = 0; ii < 8; ii++)
#pragma unroll
                for (int jj = 0; jj < 8; jj++)
                    acc[ii][jj] = fmaf(a[ii], b[jj], acc[ii][jj]);
        }
        __syncthreads();
    }

#pragma unroll
    for (int ii = 0; ii < 8; ii++) {
        int gm = m0 + ty * 8 + ii;
        if (gm >= MROWS) continue;
#pragma unroll
        for (int jj = 0; jj < 8; jj++) {
            int ng = n0 + tx * 8 + jj;
            out[(size_t)gm * CC + ng] = acc[ii][jj] + bias[ng];
        }
    }
}

// ---------------- fused flash attention with contextual RPE bias -----------
// Block: one (b,h), 64 query rows. 128 threads (ty=0..7 rows*8, tx=0..15).
// smem: Q^T [64d][68], K^T/V [64][68], P^T [64][68], Lk [64][8].
#define QLD 68
#define FLASH_SMEM ((3 * 64 * QLD + 64 * 8) * 4)

__global__ __launch_bounds__(128) void flash_kernel(const float* __restrict__ rpe_w) {
    extern __shared__ float sm[];
    float* Qst = sm;                   // d-major: Qst[d*QLD + i]
    float* KVs = sm + 64 * QLD;        // K: Kst[d*QLD + j]; V: Vs[j*QLD + d]
    float* Pst = sm + 2 * 64 * QLD;    // Pst[j*QLD + i]
    float* Lk  = sm + 3 * 64 * QLD;    // Lk[i*8 + m]

    int tid = threadIdx.x;
    int ty = tid >> 4;     // 0..7 -> rows ty*8..+7
    int tx = tid & 15;     // 0..15
    int bh = blockIdx.x;
    int b = bh / HH, h = bh - b * HH;
    int i0 = blockIdx.y * 64;

    const float* qb = g_q + (size_t)bh * NN * HD;
    const float* kb = g_k + (size_t)bh * NN * HD;
    const float* vb = g_v + (size_t)bh * NN * HD;

    int li  = tid >> 4;          // row-within-pass
    int ld4 = (tid & 15) * 4;    // d quad

    // load Q tile transposed (q already scaled)
#pragma unroll
    for (int p = 0; p < 8; p++) {
        int i = li + p * 8;
        float4 v = make_float4(0.f, 0.f, 0.f, 0.f);
        if (i0 + i < NN) v = *(const float4*)(qb + (size_t)(i0 + i) * HD + ld4);
        Qst[(ld4 + 0) * QLD + i] = v.x;
        Qst[(ld4 + 1) * QLD + i] = v.y;
        Qst[(ld4 + 2) * QLD + i] = v.z;
        Qst[(ld4 + 3) * QLD + i] = v.w;
    }
    __syncthreads();

    // per-row RPE lookup: Lk[i][m] = q_i . rpe_w[:,m]  (8 values per row)
    for (int t = tid; t < 512; t += 128) {
        int r = t >> 3, m = t & 7;
        float s = 0.f;
#pragma unroll
        for (int d = 0; d < HD; d++) s += Qst[d * QLD + r] * rpe_w[d * 8 + m];
        Lk[r * 8 + m] = s;
    }
    __syncthreads();

    float mrow[8], lrow[8], acc[8][4];
#pragma unroll
    for (int ii = 0; ii < 8; ii++) {
        mrow[ii] = -1e30f; lrow[ii] = 0.f;
#pragma unroll
        for (int c = 0; c < 4; c++) acc[ii][c] = 0.f;
    }

    for (int kt = 0; kt < 17; kt++) {
        int j0 = kt * 64;
        // K tile transposed
#pragma unroll
        for (int p = 0; p < 8; p++) {
            int j = li + p * 8;
            float4 v = make_float4(0.f, 0.f, 0.f, 0.f);
            if (j0 + j < NN) v = *(const float4*)(kb + (size_t)(j0 + j) * HD + ld4);
            KVs[(ld4 + 0) * QLD + j] = v.x;
            KVs[(ld4 + 1) * QLD + j] = v.y;
            KVs[(ld4 + 2) * QLD + j] = v.z;
            KVs[(ld4 + 3) * QLD + j] = v.w;
        }
        __syncthreads();

        // S = Q K^T  (8x4 microtile)
        float s[8][4];
#pragma unroll
        for (int ii = 0; ii < 8; ii++)
#pragma unroll
            for (int jj = 0; jj < 4; jj++) s[ii][jj] = 0.f;
#pragma unroll 4
        for (int d = 0; d < HD; d++) {
            float a[8], bb[4];
            *(float4*)&a[0]  = *(float4*)(Qst + d * QLD + ty * 8);
            *(float4*)&a[4]  = *(float4*)(Qst + d * QLD + ty * 8 + 4);
            *(float4*)&bb[0] = *(float4*)(KVs + d * QLD + tx * 4);
#pragma unroll
            for (int ii = 0; ii < 8; ii++)
#pragma unroll
                for (int jj = 0; jj < 4; jj++)
                    s[ii][jj] = fmaf(a[ii], bb[jj], s[ii][jj]);
        }

        // RPE bias (bucket gather) + OOB mask
#pragma unroll
        for (int ii = 0; ii < 8; ii++) {
            int gi = i0 + ty * 8 + ii;
#pragma unroll
            for (int jj = 0; jj < 4; jj++) {
                int gj = j0 + tx * 4 + jj;
                if (gi < NN && gj < NN) {
                    int bk = g_bucket[gi * NN + gj];
                    s[ii][jj] += Lk[(ty * 8 + ii) * 8 + bk];
                } else {
                    s[ii][jj] = -1e30f;
                }
            }
        }

        // online softmax (row groups span 16 lanes: tx = lane%16)
#pragma unroll
        for (int ii = 0; ii < 8; ii++) {
            float mt = fmaxf(fmaxf(s[ii][0], s[ii][1]), fmaxf(s[ii][2], s[ii][3]));
#pragma unroll
            for (int off = 1; off < 16; off <<= 1)
                mt = fmaxf(mt, __shfl_xor_sync(0xffffffffu, mt, off));
            float mn = fmaxf(mrow[ii], mt);
            float sum = 0.f;
#pragma unroll
            for (int jj = 0; jj < 4; jj++) {
                float pv = __expf(s[ii][jj] - mn);
                s[ii][jj] = pv;
                sum += pv;
            }
#pragma unroll
            for (int off = 1; off < 16; off <<= 1)
                sum += __shfl_xor_sync(0xffffffffu, sum, off);
            float alpha = __expf(mrow[ii] - mn);
            lrow[ii] = lrow[ii] * alpha + sum;
            mrow[ii] = mn;
#pragma unroll
            for (int c = 0; c < 4; c++) acc[ii][c] *= alpha;
        }

        // P -> smem transposed
#pragma unroll
        for (int ii = 0; ii < 8; ii++)
#pragma unroll
            for (int jj = 0; jj < 4; jj++)
                Pst[(tx * 4 + jj) * QLD + ty * 8 + ii] = s[ii][jj];
        __syncthreads();

        // V tile (reuse K buffer, natural layout)
#pragma unroll
        for (int p = 0; p < 8; p++) {
            int j = li + p * 8;
            float4 v = make_float4(0.f, 0.f, 0.f, 0.f);
            if (j0 + j < NN) v = *(const float4*)(vb + (size_t)(j0 + j) * HD + ld4);
            *(float4*)(KVs + j * QLD + ld4) = v;
        }
        __syncthreads();

        // O += P V
#pragma unroll 4
        for (int j = 0; j < 64; j++) {
            float a[8], bb[4];
            *(float4*)&a[0]  = *(float4*)(Pst + j * QLD + ty * 8);
            *(float4*)&a[4]  = *(float4*)(Pst + j * QLD + ty * 8 + 4);
            *(float4*)&bb[0] = *(float4*)(KVs + j * QLD + tx * 4);
#pragma unroll
            for (int ii = 0; ii < 8; ii++)
#pragma unroll
                for (int c = 0; c < 4; c++)
                    acc[ii][c] = fmaf(a[ii], bb[c], acc[ii][c]);
        }
        __syncthreads();
    }

    // normalize + store to [B,N,C]
#pragma unroll
    for (int ii = 0; ii < 8; ii++) {
        int gi = i0 + ty * 8 + ii;
        if (gi < NN) {
            float inv = 1.0f / lrow[ii];
#pragma unroll
            for (int c = 0; c < 4; c++)
                g_ao[((size_t)b * NN + gi) * CC + h * HD + tx * 4 + c] = acc[ii][c] * inv;
        }
    }
}

// ---------------- launch ----------------------------------------------------
extern "C" void kernel_launch(void* const* d_in, const int* in_sizes, int n_in,
                              void* d_out, int out_size) {
    (void)in_sizes; (void)n_in; (void)out_size;
    const float* x      = (const float*)d_in[0];
    const float* qkv_w  = (const float*)d_in[1];
    const float* proj_w = (const float*)d_in[2];
    const float* proj_b = (const float*)d_in[3];
    const float* rpe_w  = (const float*)d_in[4];
    float* out = (float*)d_out;

    cudaFuncSetAttribute(flash_kernel,
                         cudaFuncAttributeMaxDynamicSharedMemorySize, FLASH_SMEM);

    bucket_kernel<<<(NN * NN + 255) / 256, 256>>>();
    qkv_gemm<<<dim3(2304 / 128, (MROWS + 127) / 128), 256>>>(x, qkv_w);
    flash_kernel<<<dim3(BH, (NN + 63) / 64), 128, FLASH_SMEM>>>(rpe_w);
    proj_gemm<<<dim3(CC / 128, (MROWS + 127) / 128), 256>>>(proj_w, proj_b, out);
}

// round 4
// speedup vs baseline: 1.4603x; 1.4603x over previous
#include <cuda_runtime.h>
#include <math.h>

#define NN    1025
#define CC    768
#define HH    12
#define HD    64
#define BH    96        // B*H = 8*12
#define MROWS 8200      // B*N

// ---------------- scratch (device globals: no allocation allowed) ----------
__device__ float g_q[BH * NN * HD];      // 25.2 MB, pre-scaled by 1/8
__device__ float g_k[BH * NN * HD];
__device__ float g_v[BH * NN * HD];
__device__ float g_ao[MROWS * CC];       // attention output, [B,N,C]
__device__ unsigned char g_bucket[NN * NN];

// ---------------- bucket table (static geometry, fp64 to match numpy) ------
__global__ void bucket_kernel() {
    int idx = blockIdx.x * 256 + threadIdx.x;
    if (idx >= NN * NN) return;
    int i = idx / NN, j = idx - (idx / NN) * NN;
    int v;
    if (i == 0 || j == 0) {
        v = 7;  // cls-token bucket
    } else {
        int p = i - 1, q = j - 1;
        int dy = (p >> 5) - (q >> 5);
        int dx = (p & 31) - (q & 31);
        double dis = rint(sqrt((double)(dy * dy + dx * dx)));
        if (dis <= 1.9) {
            v = (int)dis;
        } else {
            double t = rint(1.9 + log(dis / 1.9) / log(8.0) * 1.9);
            if (t > 3.8) t = 3.8;
            v = (int)t;
        }
    }
    g_bucket[idx] = (unsigned char)v;
}

// ---------------- tf32 mma helpers -----------------------------------------
__device__ __forceinline__ unsigned f2tf(float f) {
    unsigned u;
    asm("cvt.rna.tf32.f32 %0, %1;" : "=r"(u) : "f"(f));
    return u;
}

__device__ __forceinline__ void mma_tf32(float* c, const unsigned* a, const unsigned* b) {
    asm volatile(
        "mma.sync.aligned.m16n8k8.row.col.f32.tf32.tf32.f32 "
        "{%0,%1,%2,%3}, {%4,%5,%6,%7}, {%8,%9}, {%0,%1,%2,%3};\n"
        : "+f"(c[0]), "+f"(c[1]), "+f"(c[2]), "+f"(c[3])
        : "r"(a[0]), "r"(a[1]), "r"(a[2]), "r"(a[3]), "r"(b[0]), "r"(b[1]));
}

// Shared tile layout: [row][36] floats. Fragment LDS bank index = (4g+t)%32,
// a perfect permutation over the warp -> conflict-free.
#define TLD 36

// Core: loads A[m0..m0+127][k0..+31] and W[n0..n0+127][k0..+31] (both K-major),
// converts to tf32, runs 2x4 warp grid of 64x32 warp tiles.
#define GEMM_TF32_BODY(APTR, AGUARD)                                            \
    __shared__ float As[128][TLD];                                              \
    __shared__ float Bs[128][TLD];                                              \
    int tid = threadIdx.x;                                                      \
    int lane = tid & 31, wid = tid >> 5;                                        \
    int wm = wid & 1, wn = wid >> 1;                                            \
    int g = lane >> 2, t = lane & 3;                                            \
    int m0 = blockIdx.y * 128, n0 = blockIdx.x * 128;                           \
    float acc[4][4][4];                                                         \
    _Pragma("unroll") for (int mt = 0; mt < 4; mt++)                            \
    _Pragma("unroll") for (int nt = 0; nt < 4; nt++)                            \
    _Pragma("unroll") for (int i = 0; i < 4; i++) acc[mt][nt][i] = 0.f;         \
    int lr = tid >> 3;                                                          \
    int lc = (tid & 7) * 4;                                                     \
    for (int k0 = 0; k0 < CC; k0 += 32) {                                       \
        _Pragma("unroll") for (int p = 0; p < 4; p++) {                         \
            int row = lr + p * 32;                                              \
            int gm = m0 + row;                                                  \
            float4 av = make_float4(0.f, 0.f, 0.f, 0.f);                        \
            if (AGUARD) av = *(const float4*)(APTR + (size_t)gm * CC + k0 + lc);\
            float4 as;                                                          \
            as.x = __uint_as_float(f2tf(av.x));                                 \
            as.y = __uint_as_float(f2tf(av.y));                                 \
            as.z = __uint_as_float(f2tf(av.z));                                 \
            as.w = __uint_as_float(f2tf(av.w));                                 \
            *(float4*)&As[row][lc] = as;                                        \
            float4 bv = *(const float4*)(W + (size_t)(n0 + row) * CC + k0 + lc);\
            float4 bs;                                                          \
            bs.x = __uint_as_float(f2tf(bv.x));                                 \
            bs.y = __uint_as_float(f2tf(bv.y));                                 \
            bs.z = __uint_as_float(f2tf(bv.z));                                 \
            bs.w = __uint_as_float(f2tf(bv.w));                                 \
            *(float4*)&Bs[row][lc] = bs;                                        \
        }                                                                       \
        __syncthreads();                                                        \
        _Pragma("unroll") for (int ks = 0; ks < 4; ks++) {                      \
            int kk = ks * 8;                                                    \
            unsigned af[4][4], bf[4][2];                                        \
            _Pragma("unroll") for (int mt = 0; mt < 4; mt++) {                  \
                int rb = wm * 64 + mt * 16;                                     \
                af[mt][0] = __float_as_uint(As[rb + g][kk + t]);                \
                af[mt][1] = __float_as_uint(As[rb + g + 8][kk + t]);            \
                af[mt][2] = __float_as_uint(As[rb + g][kk + t + 4]);            \
                af[mt][3] = __float_as_uint(As[rb + g + 8][kk + t + 4]);        \
            }                                                                   \
            _Pragma("unroll") for (int nt = 0; nt < 4; nt++) {                  \
                int nb = wn * 32 + nt * 8;                                      \
                bf[nt][0] = __float_as_uint(Bs[nb + g][kk + t]);                \
                bf[nt][1] = __float_as_uint(Bs[nb + g][kk + t + 4]);            \
            }                                                                   \
            _Pragma("unroll") for (int mt = 0; mt < 4; mt++)                    \
            _Pragma("unroll") for (int nt = 0; nt < 4; nt++)                    \
                mma_tf32(acc[mt][nt], af[mt], bf[nt]);                          \
        }                                                                       \
        __syncthreads();                                                        \
    }

// ---------------- QKV GEMM (tf32 tensor) ------------------------------------
// C[m][n] = sum_k X[m][k]*W[n][k]; epilogue scatters to q (x0.125) / k / v.
__global__ __launch_bounds__(256) void qkv_gemm_t(const float* __restrict__ X,
                                                  const float* __restrict__ W) {
    GEMM_TF32_BODY(X, (gm < MROWS))

#pragma unroll
    for (int mt = 0; mt < 4; mt++) {
#pragma unroll
        for (int half = 0; half < 2; half++) {
            int m = m0 + wm * 64 + mt * 16 + g + half * 8;
            if (m >= MROWS) continue;
            int b = m / NN, i = m - b * NN;
#pragma unroll
            for (int nt = 0; nt < 4; nt++) {
                int n = n0 + wn * 32 + nt * 8 + 2 * t;
                int which = n / CC;
                int cc = n - which * CC;
                int h = cc >> 6, d = cc & 63;
                size_t idx = ((size_t)(b * HH + h) * NN + i) * HD + d;
                float2 v;
                v.x = acc[mt][nt][half * 2 + 0];
                v.y = acc[mt][nt][half * 2 + 1];
                if (which == 0) {
                    v.x *= 0.125f; v.y *= 0.125f;
                    *(float2*)(g_q + idx) = v;
                } else if (which == 1) {
                    *(float2*)(g_k + idx) = v;
                } else {
                    *(float2*)(g_v + idx) = v;
                }
            }
        }
    }
}

// ---------------- proj GEMM (tf32 tensor) -----------------------------------
__global__ __launch_bounds__(256) void proj_gemm_t(const float* __restrict__ W,
                                                   const float* __restrict__ bias,
                                                   float* __restrict__ out) {
    const float* A = g_ao;
    GEMM_TF32_BODY(A, (gm < MROWS))

#pragma unroll
    for (int mt = 0; mt < 4; mt++) {
#pragma unroll
        for (int half = 0; half < 2; half++) {
            int m = m0 + wm * 64 + mt * 16 + g + half * 8;
            if (m >= MROWS) continue;
#pragma unroll
            for (int nt = 0; nt < 4; nt++) {
                int n = n0 + wn * 32 + nt * 8 + 2 * t;
                float2 v;
                v.x = acc[mt][nt][half * 2 + 0] + bias[n];
                v.y = acc[mt][nt][half * 2 + 1] + bias[n + 1];
                *(float2*)(out + (size_t)m * CC + n) = v;
            }
        }
    }
}

// ---------------- fused flash attention with contextual RPE bias -----------
#define QLD 68
#define FLASH_SMEM ((3 * 64 * QLD + 64 * 8) * 4)

__global__ __launch_bounds__(128) void flash_kernel(const float* __restrict__ rpe_w) {
    extern __shared__ float sm[];
    float* Qst = sm;                   // d-major: Qst[d*QLD + i]
    float* KVs = sm + 64 * QLD;        // K: Kst[d*QLD + j]; V: Vs[j*QLD + d]
    float* Pst = sm + 2 * 64 * QLD;    // Pst[j*QLD + i]
    float* Lk  = sm + 3 * 64 * QLD;    // Lk[i*8 + m]

    int tid = threadIdx.x;
    int ty = tid >> 4;
    int tx = tid & 15;
    int bh = blockIdx.x;
    int b = bh / HH, h = bh - b * HH;
    int i0 = blockIdx.y * 64;

    const float* qb = g_q + (size_t)bh * NN * HD;
    const float* kb = g_k + (size_t)bh * NN * HD;
    const float* vb = g_v + (size_t)bh * NN * HD;

    int li  = tid >> 4;
    int ld4 = (tid & 15) * 4;

#pragma unroll
    for (int p = 0; p < 8; p++) {
        int i = li + p * 8;
        float4 v = make_float4(0.f, 0.f, 0.f, 0.f);
        if (i0 + i < NN) v = *(const float4*)(qb + (size_t)(i0 + i) * HD + ld4);
        Qst[(ld4 + 0) * QLD + i] = v.x;
        Qst[(ld4 + 1) * QLD + i] = v.y;
        Qst[(ld4 + 2) * QLD + i] = v.z;
        Qst[(ld4 + 3) * QLD + i] = v.w;
    }
    __syncthreads();

    for (int t = tid; t < 512; t += 128) {
        int r = t >> 3, m = t & 7;
        float s = 0.f;
#pragma unroll
        for (int d = 0; d < HD; d++) s += Qst[d * QLD + r] * rpe_w[d * 8 + m];
        Lk[r * 8 + m] = s;
    }
    __syncthreads();

    float mrow[8], lrow[8], acc[8][4];
#pragma unroll
    for (int ii = 0; ii < 8; ii++) {
        mrow[ii] = -1e30f; lrow[ii] = 0.f;
#pragma unroll
        for (int c = 0; c < 4; c++) acc[ii][c] = 0.f;
    }

    for (int kt = 0; kt < 17; kt++) {
        int j0 = kt * 64;
#pragma unroll
        for (int p = 0; p < 8; p++) {
            int j = li + p * 8;
            float4 v = make_float4(0.f, 0.f, 0.f, 0.f);
            if (j0 + j < NN) v = *(const float4*)(kb + (size_t)(j0 + j) * HD + ld4);
            KVs[(ld4 + 0) * QLD + j] = v.x;
            KVs[(ld4 + 1) * QLD + j] = v.y;
            KVs[(ld4 + 2) * QLD + j] = v.z;
            KVs[(ld4 + 3) * QLD + j] = v.w;
        }
        __syncthreads();

        float s[8][4];
#pragma unroll
        for (int ii = 0; ii < 8; ii++)
#pragma unroll
            for (int jj = 0; jj < 4; jj++) s[ii][jj] = 0.f;
#pragma unroll 4
        for (int d = 0; d < HD; d++) {
            float a[8], bb[4];
            *(float4*)&a[0]  = *(float4*)(Qst + d * QLD + ty * 8);
            *(float4*)&a[4]  = *(float4*)(Qst + d * QLD + ty * 8 + 4);
            *(float4*)&bb[0] = *(float4*)(KVs + d * QLD + tx * 4);
#pragma unroll
            for (int ii = 0; ii < 8; ii++)
#pragma unroll
                for (int jj = 0; jj < 4; jj++)
                    s[ii][jj] = fmaf(a[ii], bb[jj], s[ii][jj]);
        }

#pragma unroll
        for (int ii = 0; ii < 8; ii++) {
            int gi = i0 + ty * 8 + ii;
#pragma unroll
            for (int jj = 0; jj < 4; jj++) {
                int gj = j0 + tx * 4 + jj;
                if (gi < NN && gj < NN) {
                    int bk = g_bucket[gi * NN + gj];
                    s[ii][jj] += Lk[(ty * 8 + ii) * 8 + bk];
                } else {
                    s[ii][jj] = -1e30f;
                }
            }
        }

#pragma unroll
        for (int ii = 0; ii < 8; ii++) {
            float mt = fmaxf(fmaxf(s[ii][0], s[ii][1]), fmaxf(s[ii][2], s[ii][3]));
#pragma unroll
            for (int off = 1; off < 16; off <<= 1)
                mt = fmaxf(mt, __shfl_xor_sync(0xffffffffu, mt, off));
            float mn = fmaxf(mrow[ii], mt);
            float sum = 0.f;
#pragma unroll
            for (int jj = 0; jj < 4; jj++) {
                float pv = __expf(s[ii][jj] - mn);
                s[ii][jj] = pv;
                sum += pv;
            }
#pragma unroll
            for (int off = 1; off < 16; off <<= 1)
                sum += __shfl_xor_sync(0xffffffffu, sum, off);
            float alpha = __expf(mrow[ii] - mn);
            lrow[ii] = lrow[ii] * alpha + sum;
            mrow[ii] = mn;
#pragma unroll
            for (int c = 0; c < 4; c++) acc[ii][c] *= alpha;
        }

#pragma unroll
        for (int ii = 0; ii < 8; ii++)
#pragma unroll
            for (int jj = 0; jj < 4; jj++)
                Pst[(tx * 4 + jj) * QLD + ty * 8 + ii] = s[ii][jj];
        __syncthreads();

#pragma unroll
        for (int p = 0; p < 8; p++) {
            int j = li + p * 8;
            float4 v = make_float4(0.f, 0.f, 0.f, 0.f);
            if (j0 + j < NN) v = *(const float4*)(vb + (size_t)(j0 + j) * HD + ld4);
            *(float4*)(KVs + j * QLD + ld4) = v;
        }
        __syncthreads();

#pragma unroll 4
        for (int j = 0; j < 64; j++) {
            float a[8], bb[4];
            *(float4*)&a[0]  = *(float4*)(Pst + j * QLD + ty * 8);
            *(float4*)&a[4]  = *(float4*)(Pst + j * QLD + ty * 8 + 4);
            *(float4*)&bb[0] = *(float4*)(KVs + j * QLD + tx * 4);
#pragma unroll
            for (int ii = 0; ii < 8; ii++)
#pragma unroll
                for (int c = 0; c < 4; c++)
                    acc[ii][c] = fmaf(a[ii], bb[c], acc[ii][c]);
        }
        __syncthreads();
    }

#pragma unroll
    for (int ii = 0; ii < 8; ii++) {
        int gi = i0 + ty * 8 + ii;
        if (gi < NN) {
            float inv = 1.0f / lrow[ii];
#pragma unroll
            for (int c = 0; c < 4; c++)
                g_ao[((size_t)b * NN + gi) * CC + h * HD + tx * 4 + c] = acc[ii][c] * inv;
        }
    }
}

// ---------------- launch ----------------------------------------------------
extern "C" void kernel_launch(void* const* d_in, const int* in_sizes, int n_in,
                              void* d_out, int out_size) {
    (void)in_sizes; (void)n_in; (void)out_size;
    const float* x      = (const float*)d_in[0];
    const float* qkv_w  = (const float*)d_in[1];
    const float* proj_w = (const float*)d_in[2];
    const float* proj_b = (const float*)d_in[3];
    const float* rpe_w  = (const float*)d_in[4];
    float* out = (float*)d_out;

    cudaFuncSetAttribute(flash_kernel,
                         cudaFuncAttributeMaxDynamicSharedMemorySize, FLASH_SMEM);

    bucket_kernel<<<(NN * NN + 255) / 256, 256>>>();
    qkv_gemm_t<<<dim3(2304 / 128, (MROWS + 127) / 128), 256>>>(x, qkv_w);
    flash_kernel<<<dim3(BH, (NN + 63) / 64), 128, FLASH_SMEM>>>(rpe_w);
    proj_gemm_t<<<dim3(CC / 128, (MROWS + 127) / 128), 256>>>(proj_w, proj_b, out);
}

// round 5
// speedup vs baseline: 1.8352x; 1.2567x over previous
#include <cuda_runtime.h>
#include <math.h>

#define NN    1025
#define CC    768
#define HH    12
#define HD    64
#define BH    96        // B*H = 8*12
#define MROWS 8200      // B*N

// ---------------- scratch (device globals: no allocation allowed) ----------
__device__ float g_q[BH * NN * HD];      // pre-scaled by 1/8
__device__ float g_k[BH * NN * HD];
__device__ float g_v[BH * NN * HD];
__device__ float g_ao[MROWS * CC];       // attention output, [B,N,C]
__device__ unsigned char g_bucket[NN * NN];

// ---------------- bucket table (static geometry, fp64 to match numpy) ------
__global__ void bucket_kernel() {
    int idx = blockIdx.x * 256 + threadIdx.x;
    if (idx >= NN * NN) return;
    int i = idx / NN, j = idx - (idx / NN) * NN;
    int v;
    if (i == 0 || j == 0) {
        v = 7;  // cls-token bucket
    } else {
        int p = i - 1, q = j - 1;
        int dy = (p >> 5) - (q >> 5);
        int dx = (p & 31) - (q & 31);
        double dis = rint(sqrt((double)(dy * dy + dx * dx)));
        if (dis <= 1.9) {
            v = (int)dis;
        } else {
            double t = rint(1.9 + log(dis / 1.9) / log(8.0) * 1.9);
            if (t > 3.8) t = 3.8;
            v = (int)t;
        }
    }
    g_bucket[idx] = (unsigned char)v;
}

// ---------------- tf32 mma helpers -----------------------------------------
__device__ __forceinline__ unsigned f2tf(float f) {
    unsigned u;
    asm("cvt.rna.tf32.f32 %0, %1;" : "=r"(u) : "f"(f));
    return u;
}

__device__ __forceinline__ void mma_tf32(float* c, const unsigned* a, const unsigned* b) {
    asm volatile(
        "mma.sync.aligned.m16n8k8.row.col.f32.tf32.tf32.f32 "
        "{%0,%1,%2,%3}, {%4,%5,%6,%7}, {%8,%9}, {%0,%1,%2,%3};\n"
        : "+f"(c[0]), "+f"(c[1]), "+f"(c[2]), "+f"(c[3])
        : "r"(a[0]), "r"(a[1]), "r"(a[2]), "r"(a[3]), "r"(b[0]), "r"(b[1]));
}

// Shared tile layout: [row][36] floats. Fragment LDS bank index = (4g+t)%32.
#define TLD 36

#define GEMM_TF32_BODY(APTR, AGUARD)                                            \
    __shared__ float As[128][TLD];                                              \
    __shared__ float Bs[128][TLD];                                              \
    int tid = threadIdx.x;                                                      \
    int lane = tid & 31, wid = tid >> 5;                                        \
    int wm = wid & 1, wn = wid >> 1;                                            \
    int g = lane >> 2, t = lane & 3;                                            \
    int m0 = blockIdx.y * 128, n0 = blockIdx.x * 128;                           \
    float acc[4][4][4];                                                         \
    _Pragma("unroll") for (int mt = 0; mt < 4; mt++)                            \
    _Pragma("unroll") for (int nt = 0; nt < 4; nt++)                            \
    _Pragma("unroll") for (int i = 0; i < 4; i++) acc[mt][nt][i] = 0.f;         \
    int lr = tid >> 3;                                                          \
    int lc = (tid & 7) * 4;                                                     \
    for (int k0 = 0; k0 < CC; k0 += 32) {                                       \
        _Pragma("unroll") for (int p = 0; p < 4; p++) {                         \
            int row = lr + p * 32;                                              \
            int gm = m0 + row;                                                  \
            float4 av = make_float4(0.f, 0.f, 0.f, 0.f);                        \
            if (AGUARD) av = *(const float4*)(APTR + (size_t)gm * CC + k0 + lc);\
            float4 as;                                                          \
            as.x = __uint_as_float(f2tf(av.x));                                 \
            as.y = __uint_as_float(f2tf(av.y));                                 \
            as.z = __uint_as_float(f2tf(av.z));                                 \
            as.w = __uint_as_float(f2tf(av.w));                                 \
            *(float4*)&As[row][lc] = as;                                        \
            float4 bv = *(const float4*)(W + (size_t)(n0 + row) * CC + k0 + lc);\
            float4 bs;                                                          \
            bs.x = __uint_as_float(f2tf(bv.x));                                 \
            bs.y = __uint_as_float(f2tf(bv.y));                                 \
            bs.z = __uint_as_float(f2tf(bv.z));                                 \
            bs.w = __uint_as_float(f2tf(bv.w));                                 \
            *(float4*)&Bs[row][lc] = bs;                                        \
        }                                                                       \
        __syncthreads();                                                        \
        _Pragma("unroll") for (int ks = 0; ks < 4; ks++) {                      \
            int kk = ks * 8;                                                    \
            unsigned af[4][4], bf[4][2];                                        \
            _Pragma("unroll") for (int mt = 0; mt < 4; mt++) {                  \
                int rb = wm * 64 + mt * 16;                                     \
                af[mt][0] = __float_as_uint(As[rb + g][kk + t]);                \
                af[mt][1] = __float_as_uint(As[rb + g + 8][kk + t]);            \
                af[mt][2] = __float_as_uint(As[rb + g][kk + t + 4]);            \
                af[mt][3] = __float_as_uint(As[rb + g + 8][kk + t + 4]);        \
            }                                                                   \
            _Pragma("unroll") for (int nt = 0; nt < 4; nt++) {                  \
                int nb = wn * 32 + nt * 8;                                      \
                bf[nt][0] = __float_as_uint(Bs[nb + g][kk + t]);                \
                bf[nt][1] = __float_as_uint(Bs[nb + g][kk + t + 4]);            \
            }                                                                   \
            _Pragma("unroll") for (int mt = 0; mt < 4; mt++)                    \
            _Pragma("unroll") for (int nt = 0; nt < 4; nt++)                    \
                mma_tf32(acc[mt][nt], af[mt], bf[nt]);                          \
        }                                                                       \
        __syncthreads();                                                        \
    }

// ---------------- QKV GEMM (tf32 tensor) ------------------------------------
__global__ __launch_bounds__(256) void qkv_gemm_t(const float* __restrict__ X,
                                                  const float* __restrict__ W) {
    GEMM_TF32_BODY(X, (gm < MROWS))

#pragma unroll
    for (int mt = 0; mt < 4; mt++) {
#pragma unroll
        for (int half = 0; half < 2; half++) {
            int m = m0 + wm * 64 + mt * 16 + g + half * 8;
            if (m >= MROWS) continue;
            int b = m / NN, i = m - b * NN;
#pragma unroll
            for (int nt = 0; nt < 4; nt++) {
                int n = n0 + wn * 32 + nt * 8 + 2 * t;
                int which = n / CC;
                int cc = n - which * CC;
                int h = cc >> 6, d = cc & 63;
                size_t idx = ((size_t)(b * HH + h) * NN + i) * HD + d;
                float2 v;
                v.x = acc[mt][nt][half * 2 + 0];
                v.y = acc[mt][nt][half * 2 + 1];
                if (which == 0) {
                    v.x *= 0.125f; v.y *= 0.125f;
                    *(float2*)(g_q + idx) = v;
                } else if (which == 1) {
                    *(float2*)(g_k + idx) = v;
                } else {
                    *(float2*)(g_v + idx) = v;
                }
            }
        }
    }
}

// ---------------- proj GEMM (tf32 tensor) -----------------------------------
__global__ __launch_bounds__(256) void proj_gemm_t(const float* __restrict__ W,
                                                   const float* __restrict__ bias,
                                                   float* __restrict__ out) {
    const float* A = g_ao;
    GEMM_TF32_BODY(A, (gm < MROWS))

#pragma unroll
    for (int mt = 0; mt < 4; mt++) {
#pragma unroll
        for (int half = 0; half < 2; half++) {
            int m = m0 + wm * 64 + mt * 16 + g + half * 8;
            if (m >= MROWS) continue;
#pragma unroll
            for (int nt = 0; nt < 4; nt++) {
                int n = n0 + wn * 32 + nt * 8 + 2 * t;
                float2 v;
                v.x = acc[mt][nt][half * 2 + 0] + bias[n];
                v.y = acc[mt][nt][half * 2 + 1] + bias[n + 1];
                *(float2*)(out + (size_t)m * CC + n) = v;
            }
        }
    }
}

// ---------------- flash attention, tf32 mma, contextual RPE bias -----------
// Block: one (b,h) x 64 q-rows; 128 threads (4 warps x 16 rows).
// smem: Qs[64][68] (row-major, tf32), Ks[64][68] (K rows, later V^T), Ps[64][68], Lk[64][8].
#define QLD 68
#define FLASH_SMEM ((3 * 64 * QLD + 64 * 8) * 4)

__global__ __launch_bounds__(128, 4) void flash_mma(const float* __restrict__ rpe_w) {
    extern __shared__ float sm[];
    float* Qs = sm;
    float* Ks = sm + 64 * QLD;
    float* Ps = sm + 2 * 64 * QLD;
    float* Lk = sm + 3 * 64 * QLD;

    int tid = threadIdx.x;
    int lane = tid & 31, w = tid >> 5;
    int g = lane >> 2, t = lane & 3;
    int bh = blockIdx.x;
    int b = bh / HH, h = bh - b * HH;
    int i0 = blockIdx.y * 64;

    const float* qb = g_q + (size_t)bh * NN * HD;
    const float* kb = g_k + (size_t)bh * NN * HD;
    const float* vb = g_v + (size_t)bh * NN * HD;

    int li  = tid >> 4;          // 0..7
    int ld4 = (tid & 15) * 4;    // 0..60

    // Q tile, row-major, tf32-converted
#pragma unroll
    for (int p = 0; p < 8; p++) {
        int r = li + p * 8;
        float4 v = make_float4(0.f, 0.f, 0.f, 0.f);
        if (i0 + r < NN) v = *(const float4*)(qb + (size_t)(i0 + r) * HD + ld4);
        float4 c;
        c.x = __uint_as_float(f2tf(v.x));
        c.y = __uint_as_float(f2tf(v.y));
        c.z = __uint_as_float(f2tf(v.z));
        c.w = __uint_as_float(f2tf(v.w));
        *(float4*)(Qs + r * QLD + ld4) = c;
    }
    __syncthreads();

    // per-row RPE lookup: Lk[r][m] = q_r . rpe_w[:,m]
    for (int tq = tid; tq < 512; tq += 128) {
        int r = tq >> 3, m = tq & 7;
        float s = 0.f;
#pragma unroll
        for (int d = 0; d < HD; d++) s += Qs[r * QLD + d] * rpe_w[d * 8 + m];
        Lk[r * 8 + m] = s;
    }
    __syncthreads();

    int rl0 = w * 16 + g;        // local row for c0/c1 (c2/c3 = rl0+8)
    int gr0 = i0 + rl0, gr1 = gr0 + 8;
    bool v0 = gr0 < NN, v1 = gr1 < NN;
    const unsigned char* br0 = g_bucket + (size_t)gr0 * NN;
    const unsigned char* br1 = g_bucket + (size_t)gr1 * NN;

    float m0 = -1e30f, m1 = -1e30f, l0 = 0.f, l1 = 0.f;
    float oacc[8][4];
#pragma unroll
    for (int nt = 0; nt < 8; nt++)
#pragma unroll
        for (int c = 0; c < 4; c++) oacc[nt][c] = 0.f;

    for (int kt = 0; kt < 17; kt++) {
        int j0 = kt * 64;

        // K tile, row-major, tf32
#pragma unroll
        for (int p = 0; p < 8; p++) {
            int r = li + p * 8;
            float4 v = make_float4(0.f, 0.f, 0.f, 0.f);
            if (j0 + r < NN) v = *(const float4*)(kb + (size_t)(j0 + r) * HD + ld4);
            float4 c;
            c.x = __uint_as_float(f2tf(v.x));
            c.y = __uint_as_float(f2tf(v.y));
            c.z = __uint_as_float(f2tf(v.z));
            c.w = __uint_as_float(f2tf(v.w));
            *(float4*)(Ks + r * QLD + ld4) = c;
        }
        __syncthreads();

        // S = Q K^T
        float sacc[8][4];
#pragma unroll
        for (int nt = 0; nt < 8; nt++)
#pragma unroll
            for (int c = 0; c < 4; c++) sacc[nt][c] = 0.f;
#pragma unroll
        for (int ks = 0; ks < 8; ks++) {
            int kk = ks * 8;
            unsigned a[4];
            a[0] = __float_as_uint(Qs[rl0 * QLD + kk + t]);
            a[1] = __float_as_uint(Qs[(rl0 + 8) * QLD + kk + t]);
            a[2] = __float_as_uint(Qs[rl0 * QLD + kk + t + 4]);
            a[3] = __float_as_uint(Qs[(rl0 + 8) * QLD + kk + t + 4]);
#pragma unroll
            for (int nt = 0; nt < 8; nt++) {
                unsigned bf[2];
                bf[0] = __float_as_uint(Ks[(nt * 8 + g) * QLD + kk + t]);
                bf[1] = __float_as_uint(Ks[(nt * 8 + g) * QLD + kk + t + 4]);
                mma_tf32(sacc[nt], a, bf);
            }
        }

        // RPE bias gather + OOB mask
#pragma unroll
        for (int nt = 0; nt < 8; nt++) {
            int j = j0 + nt * 8 + 2 * t;
            if (j < NN) {
                if (v0) sacc[nt][0] += Lk[rl0 * 8 + br0[j]];
                if (v1) sacc[nt][2] += Lk[(rl0 + 8) * 8 + br1[j]];
            } else { sacc[nt][0] = -1e30f; sacc[nt][2] = -1e30f; }
            if (j + 1 < NN) {
                if (v0) sacc[nt][1] += Lk[rl0 * 8 + br0[j + 1]];
                if (v1) sacc[nt][3] += Lk[(rl0 + 8) * 8 + br1[j + 1]];
            } else { sacc[nt][1] = -1e30f; sacc[nt][3] = -1e30f; }
        }

        // online softmax; rows owned by 4-lane quads (shfl xor 1,2)
        float mt0 = -1e30f, mt1 = -1e30f;
#pragma unroll
        for (int nt = 0; nt < 8; nt++) {
            mt0 = fmaxf(mt0, fmaxf(sacc[nt][0], sacc[nt][1]));
            mt1 = fmaxf(mt1, fmaxf(sacc[nt][2], sacc[nt][3]));
        }
        mt0 = fmaxf(mt0, __shfl_xor_sync(0xffffffffu, mt0, 1));
        mt0 = fmaxf(mt0, __shfl_xor_sync(0xffffffffu, mt0, 2));
        mt1 = fmaxf(mt1, __shfl_xor_sync(0xffffffffu, mt1, 1));
        mt1 = fmaxf(mt1, __shfl_xor_sync(0xffffffffu, mt1, 2));
        float mn0 = fmaxf(m0, mt0), mn1 = fmaxf(m1, mt1);
        float al0 = __expf(m0 - mn0), al1 = __expf(m1 - mn1);
        float s0 = 0.f, s1 = 0.f;
#pragma unroll
        for (int nt = 0; nt < 8; nt++) {
            float p0 = __expf(sacc[nt][0] - mn0);
            float p1 = __expf(sacc[nt][1] - mn0);
            float p2 = __expf(sacc[nt][2] - mn1);
            float p3 = __expf(sacc[nt][3] - mn1);
            s0 += p0 + p1; s1 += p2 + p3;
            int cb = nt * 8 + 2 * t;
            Ps[rl0 * QLD + cb]           = __uint_as_float(f2tf(p0));
            Ps[rl0 * QLD + cb + 1]       = __uint_as_float(f2tf(p1));
            Ps[(rl0 + 8) * QLD + cb]     = __uint_as_float(f2tf(p2));
            Ps[(rl0 + 8) * QLD + cb + 1] = __uint_as_float(f2tf(p3));
        }
        s0 += __shfl_xor_sync(0xffffffffu, s0, 1);
        s0 += __shfl_xor_sync(0xffffffffu, s0, 2);
        s1 += __shfl_xor_sync(0xffffffffu, s1, 1);
        s1 += __shfl_xor_sync(0xffffffffu, s1, 2);
        l0 = l0 * al0 + s0; m0 = mn0;
        l1 = l1 * al1 + s1; m1 = mn1;
#pragma unroll
        for (int nt = 0; nt < 8; nt++) {
            oacc[nt][0] *= al0; oacc[nt][1] *= al0;
            oacc[nt][2] *= al1; oacc[nt][3] *= al1;
        }
        __syncthreads();   // all warps done reading Ks; Ps written

        // V^T into Ks: Vt[d][j], tf32
#pragma unroll
        for (int p = 0; p < 8; p++) {
            int r = li + p * 8;
            float4 v = make_float4(0.f, 0.f, 0.f, 0.f);
            if (j0 + r < NN) v = *(const float4*)(vb + (size_t)(j0 + r) * HD + ld4);
            Ks[(ld4 + 0) * QLD + r] = __uint_as_float(f2tf(v.x));
            Ks[(ld4 + 1) * QLD + r] = __uint_as_float(f2tf(v.y));
            Ks[(ld4 + 2) * QLD + r] = __uint_as_float(f2tf(v.z));
            Ks[(ld4 + 3) * QLD + r] = __uint_as_float(f2tf(v.w));
        }
        __syncthreads();

        // O += P @ V   (A=P row-major, B=Vt[n=d][k=j])
#pragma unroll
        for (int ks = 0; ks < 8; ks++) {
            int kk = ks * 8;
            unsigned a[4];
            a[0] = __float_as_uint(Ps[rl0 * QLD + kk + t]);
            a[1] = __float_as_uint(Ps[(rl0 + 8) * QLD + kk + t]);
            a[2] = __float_as_uint(Ps[rl0 * QLD + kk + t + 4]);
            a[3] = __float_as_uint(Ps[(rl0 + 8) * QLD + kk + t + 4]);
#pragma unroll
            for (int nt = 0; nt < 8; nt++) {
                unsigned bf[2];
                bf[0] = __float_as_uint(Ks[(nt * 8 + g) * QLD + kk + t]);
                bf[1] = __float_as_uint(Ks[(nt * 8 + g) * QLD + kk + t + 4]);
                mma_tf32(oacc[nt], a, bf);
            }
        }
        __syncthreads();   // before next K load overwrites Ks
    }

    // normalize + store to [B,N,C]
    if (v0) {
        float inv = 1.0f / l0;
#pragma unroll
        for (int nt = 0; nt < 8; nt++) {
            float2 o;
            o.x = oacc[nt][0] * inv; o.y = oacc[nt][1] * inv;
            *(float2*)(g_ao + ((size_t)b * NN + gr0) * CC + h * HD + nt * 8 + 2 * t) = o;
        }
    }
    if (v1) {
        float inv = 1.0f / l1;
#pragma unroll
        for (int nt = 0; nt < 8; nt++) {
            float2 o;
            o.x = oacc[nt][2] * inv; o.y = oacc[nt][3] * inv;
            *(float2*)(g_ao + ((size_t)b * NN + gr1) * CC + h * HD + nt * 8 + 2 * t) = o;
        }
    }
}

// ---------------- launch ----------------------------------------------------
extern "C" void kernel_launch(void* const* d_in, const int* in_sizes, int n_in,
                              void* d_out, int out_size) {
    (void)in_sizes; (void)n_in; (void)out_size;
    const float* x      = (const float*)d_in[0];
    const float* qkv_w  = (const float*)d_in[1];
    const float* proj_w = (const float*)d_in[2];
    const float* proj_b = (const float*)d_in[3];
    const float* rpe_w  = (const float*)d_in[4];
    float* out = (float*)d_out;

    cudaFuncSetAttribute(flash_mma,
                         cudaFuncAttributeMaxDynamicSharedMemorySize, FLASH_SMEM);

    bucket_kernel<<<(NN * NN + 255) / 256, 256>>>();
    qkv_gemm_t<<<dim3(2304 / 128, (MROWS + 127) / 128), 256>>>(x, qkv_w);
    flash_mma<<<dim3(BH, (NN + 63) / 64), 128, FLASH_SMEM>>>(rpe_w);
    proj_gemm_t<<<dim3(CC / 128, (MROWS + 127) / 128), 256>>>(proj_w, proj_b, out);
}

// round 8
// speedup vs baseline: 2.1990x; 1.1982x over previous
#include <cuda_runtime.h>
#include <math.h>

#define NN    1025
#define CC    768
#define HH    12
#define HD    64
#define BH    96        // B*H
#define MROWS 8200      // B*N
#define NKV   1088      // 17*64  (kv padding)
#define NQP   1152      // 9*128  (q padding)

// ---------------- scratch (device globals, zero-initialized) ---------------
__device__ float g_q[BH * NQP * HD];     // tf32-rounded, pre-scaled by 1/8, padded rows = 0
__device__ float g_k[BH * NKV * HD];     // tf32-rounded, padded rows = 0
__device__ float g_vt[BH * HD * NKV];    // V transposed [bh][d][j], tf32, padded cols = 0
__device__ float g_ao[MROWS * CC];       // attention output, [B,N,C]
__device__ unsigned char g_bucket[NN * NN];

// ---------------- bucket table (static geometry, fp64 to match numpy) ------
__global__ void bucket_kernel() {
    int idx = blockIdx.x * 256 + threadIdx.x;
    if (idx >= NN * NN) return;
    int i = idx / NN, j = idx - (idx / NN) * NN;
    int v;
    if (i == 0 || j == 0) {
        v = 7;
    } else {
        int p = i - 1, q = j - 1;
        int dy = (p >> 5) - (q >> 5);
        int dx = (p & 31) - (q & 31);
        double dis = rint(sqrt((double)(dy * dy + dx * dx)));
        if (dis <= 1.9) {
            v = (int)dis;
        } else {
            double t = rint(1.9 + log(dis / 1.9) / log(8.0) * 1.9);
            if (t > 3.8) t = 3.8;
            v = (int)t;
        }
    }
    g_bucket[idx] = (unsigned char)v;
}

// ---------------- tf32 mma helpers -----------------------------------------
__device__ __forceinline__ unsigned f2tf(float f) {
    unsigned u;
    asm("cvt.rna.tf32.f32 %0, %1;" : "=r"(u) : "f"(f));
    return u;
}
__device__ __forceinline__ float f2tff(float f) { return __uint_as_float(f2tf(f)); }

__device__ __forceinline__ void mma_tf32(float* c, const unsigned* a, const unsigned* b) {
    asm volatile(
        "mma.sync.aligned.m16n8k8.row.col.f32.tf32.tf32.f32 "
        "{%0,%1,%2,%3}, {%4,%5,%6,%7}, {%8,%9}, {%0,%1,%2,%3};\n"
        : "+f"(c[0]), "+f"(c[1]), "+f"(c[2]), "+f"(c[3])
        : "r"(a[0]), "r"(a[1]), "r"(a[2]), "r"(a[3]), "r"(b[0]), "r"(b[1]));
}

__device__ __forceinline__ void cp16(float* dst, const float* src) {
    unsigned d = (unsigned)__cvta_generic_to_shared(dst);
    asm volatile("cp.async.cg.shared.global [%0], [%1], 16;" :: "r"(d), "l"(src));
}
#define CP_COMMIT() asm volatile("cp.async.commit_group;")
#define CP_WAIT0()  asm volatile("cp.async.wait_group 0;" ::: "memory")

// ---------------- dense GEMM core (tf32 tensor) -----------------------------
#define TLD 36

#define GEMM_TF32_BODY(APTR, AGUARD)                                            \
    __shared__ float As[128][TLD];                                              \
    __shared__ float Bs[128][TLD];                                              \
    int tid = threadIdx.x;                                                      \
    int lane = tid & 31, wid = tid >> 5;                                        \
    int wm = wid & 1, wn = wid >> 1;                                            \
    int g = lane >> 2, t = lane & 3;                                            \
    int m0 = blockIdx.y * 128, n0 = blockIdx.x * 128;                           \
    float acc[4][4][4];                                                         \
    _Pragma("unroll") for (int mt = 0; mt < 4; mt++)                            \
    _Pragma("unroll") for (int nt = 0; nt < 4; nt++)                            \
    _Pragma("unroll") for (int i = 0; i < 4; i++) acc[mt][nt][i] = 0.f;         \
    int lr = tid >> 3;                                                          \
    int lc = (tid & 7) * 4;                                                     \
    for (int k0 = 0; k0 < CC; k0 += 32) {                                       \
        _Pragma("unroll") for (int p = 0; p < 4; p++) {                         \
            int row = lr + p * 32;                                              \
            int gm = m0 + row;                                                  \
            float4 av = make_float4(0.f, 0.f, 0.f, 0.f);                        \
            if (AGUARD) av = *(const float4*)(APTR + (size_t)gm * CC + k0 + lc);\
            float4 as;                                                          \
            as.x = f2tff(av.x); as.y = f2tff(av.y);                             \
            as.z = f2tff(av.z); as.w = f2tff(av.w);                             \
            *(float4*)&As[row][lc] = as;                                        \
            float4 bv = *(const float4*)(W + (size_t)(n0 + row) * CC + k0 + lc);\
            float4 bs;                                                          \
            bs.x = f2tff(bv.x); bs.y = f2tff(bv.y);                             \
            bs.z = f2tff(bv.z); bs.w = f2tff(bv.w);                             \
            *(float4*)&Bs[row][lc] = bs;                                        \
        }                                                                       \
        __syncthreads();                                                        \
        _Pragma("unroll") for (int ks = 0; ks < 4; ks++) {                      \
            int kk = ks * 8;                                                    \
            unsigned af[4][4], bf[4][2];                                        \
            _Pragma("unroll") for (int mt = 0; mt < 4; mt++) {                  \
                int rb = wm * 64 + mt * 16;                                     \
                af[mt][0] = __float_as_uint(As[rb + g][kk + t]);                \
                af[mt][1] = __float_as_uint(As[rb + g + 8][kk + t]);            \
                af[mt][2] = __float_as_uint(As[rb + g][kk + t + 4]);            \
                af[mt][3] = __float_as_uint(As[rb + g + 8][kk + t + 4]);        \
            }                                                                   \
            _Pragma("unroll") for (int nt = 0; nt < 4; nt++) {                  \
                int nb = wn * 32 + nt * 8;                                      \
                bf[nt][0] = __float_as_uint(Bs[nb + g][kk + t]);                \
                bf[nt][1] = __float_as_uint(Bs[nb + g][kk + t + 4]);            \
            }                                                                   \
            _Pragma("unroll") for (int mt = 0; mt < 4; mt++)                    \
            _Pragma("unroll") for (int nt = 0; nt < 4; nt++)                    \
                mma_tf32(acc[mt][nt], af[mt], bf[nt]);                          \
        }                                                                       \
        __syncthreads();                                                        \
    }

// ---------------- QKV GEMM ---------------------------------------------------
// Epilogue: q -> g_q (scaled, tf32, [bh][i][d], NQP rows)
//           k -> g_k (tf32, [bh][i][d], NKV rows)
//           v -> g_vt (tf32, TRANSPOSED [bh][d][j], NKV cols)
__global__ __launch_bounds__(256) void qkv_gemm_t(const float* __restrict__ X,
                                                  const float* __restrict__ W) {
    GEMM_TF32_BODY(X, (gm < MROWS))

#pragma unroll
    for (int mt = 0; mt < 4; mt++) {
#pragma unroll
        for (int half = 0; half < 2; half++) {
            int m = m0 + wm * 64 + mt * 16 + g + half * 8;
            if (m >= MROWS) continue;
            int b = m / NN, i = m - b * NN;
#pragma unroll
            for (int nt = 0; nt < 4; nt++) {
                int n = n0 + wn * 32 + nt * 8 + 2 * t;
                int which = n / CC;
                int cc = n - which * CC;
                int h = cc >> 6, d = cc & 63;
                int bhv = b * HH + h;
                float vx = acc[mt][nt][half * 2 + 0];
                float vy = acc[mt][nt][half * 2 + 1];
                if (which == 0) {
                    float2 v;
                    v.x = f2tff(vx * 0.125f);
                    v.y = f2tff(vy * 0.125f);
                    *(float2*)(g_q + ((size_t)bhv * NQP + i) * HD + d) = v;
                } else if (which == 1) {
                    float2 v;
                    v.x = f2tff(vx); v.y = f2tff(vy);
                    *(float2*)(g_k + ((size_t)bhv * NKV + i) * HD + d) = v;
                } else {
                    size_t base = (size_t)bhv * HD;
                    g_vt[(base + d) * NKV + i]     = f2tff(vx);
                    g_vt[(base + d + 1) * NKV + i] = f2tff(vy);
                }
            }
        }
    }
}

// ---------------- proj GEMM --------------------------------------------------
__global__ __launch_bounds__(256) void proj_gemm_t(const float* __restrict__ W,
                                                   const float* __restrict__ bias,
                                                   float* __restrict__ out) {
    const float* A = g_ao;
    GEMM_TF32_BODY(A, (gm < MROWS))

#pragma unroll
    for (int mt = 0; mt < 4; mt++) {
#pragma unroll
        for (int half = 0; half < 2; half++) {
            int m = m0 + wm * 64 + mt * 16 + g + half * 8;
            if (m >= MROWS) continue;
#pragma unroll
            for (int nt = 0; nt < 4; nt++) {
                int n = n0 + wn * 32 + nt * 8 + 2 * t;
                float2 v;
                v.x = acc[mt][nt][half * 2 + 0] + bias[n];
                v.y = acc[mt][nt][half * 2 + 1] + bias[n + 1];
                *(float2*)(out + (size_t)m * CC + n) = v;
            }
        }
    }
}

// ---------------- flash attention, tf32 mma, 128-row q-blocks ---------------
// 128 threads = 4 warps; warp w owns 32 q-rows (2 m-tiles). 9 q-blocks per bh.
#define QLD 68
#define SM_KS (128 * QLD)
#define SM_VS (SM_KS + 64 * QLD)
#define SM_PS (SM_VS + 64 * QLD)
#define SM_LK (SM_PS + 128 * QLD)
#define FLASH_SMEM ((SM_LK + 128 * 8) * 4)

__global__ void __launch_bounds__(128, 2) flash_mma(const float* __restrict__ rpe_w) {
    extern __shared__ float sm[];
    float* Qs = sm;
    float* Ks = sm + SM_KS;
    float* Vs = sm + SM_VS;
    float* Ps = sm + SM_PS;
    float* Lk = sm + SM_LK;

    int tid = threadIdx.x;
    int lane = tid & 31, w = tid >> 5;
    int g = lane >> 2, t = lane & 3;
    int bh = blockIdx.x;
    int b = bh / HH, h = bh - b * HH;
    int i0 = blockIdx.y * 128;

    const float* qb  = g_q  + (size_t)bh * NQP * HD;
    const float* kb  = g_k  + (size_t)bh * NKV * HD;
    const float* vtb = g_vt + (size_t)bh * HD * NKV;

    // Q tile: 128 rows x 64 floats (pre-converted, padded) via cp.async
#pragma unroll
    for (int c = 0; c < 16; c++) {
        int ch = tid + c * 128;
        int r = ch >> 4, q = ch & 15;
        cp16(Qs + r * QLD + q * 4, qb + (size_t)(i0 + r) * HD + q * 4);
    }
    CP_COMMIT(); CP_WAIT0(); __syncthreads();

    // per-row RPE lookup table
    for (int tq = tid; tq < 1024; tq += 128) {
        int r = tq >> 3, m = tq & 7;
        float s = 0.f;
#pragma unroll
        for (int d = 0; d < HD; d++) s += Qs[r * QLD + d] * rpe_w[d * 8 + m];
        Lk[r * 8 + m] = s;
    }
    __syncthreads();

    int rl = w * 32 + g;
    int grow[4];
    const unsigned char* br[4];
#pragma unroll
    for (int s = 0; s < 4; s++) {
        int r = i0 + rl + (s >> 1) * 16 + (s & 1) * 8;   // s = mt*2 + half
        grow[s] = r;
        int rc = r < NN ? r : NN - 1;
        br[s] = g_bucket + (size_t)rc * NN;
    }

    float mx[4], ll[4];
#pragma unroll
    for (int s = 0; s < 4; s++) { mx[s] = -1e30f; ll[s] = 0.f; }
    float oacc[2][8][4];
#pragma unroll
    for (int mt = 0; mt < 2; mt++)
#pragma unroll
        for (int nt = 0; nt < 8; nt++)
#pragma unroll
            for (int c = 0; c < 4; c++) oacc[mt][nt][c] = 0.f;

    for (int kt = 0; kt < 17; kt++) {
        int j0 = kt * 64;
        // prefetch K rows + V^T rows (both padded, unguarded)
#pragma unroll
        for (int c = 0; c < 8; c++) {
            int ch = tid + c * 128;
            int r = ch >> 4, q = ch & 15;
            cp16(Ks + r * QLD + q * 4, kb + (size_t)(j0 + r) * HD + q * 4);
        }
#pragma unroll
        for (int c = 0; c < 8; c++) {
            int ch = tid + c * 128;
            int r = ch >> 4, q = ch & 15;
            cp16(Vs + r * QLD + q * 4, vtb + (size_t)r * NKV + j0 + q * 4);
        }
        CP_COMMIT(); CP_WAIT0(); __syncthreads();

        // S = Q K^T, 2 m-tiles per warp
        float sacc[2][8][4];
#pragma unroll
        for (int mt = 0; mt < 2; mt++)
#pragma unroll
            for (int nt = 0; nt < 8; nt++)
#pragma unroll
                for (int c = 0; c < 4; c++) sacc[mt][nt][c] = 0.f;
#pragma unroll
        for (int ks = 0; ks < 8; ks++) {
            int kk = ks * 8;
            unsigned a0[4], a1[4];
            a0[0] = __float_as_uint(Qs[(rl)      * QLD + kk + t]);
            a0[1] = __float_as_uint(Qs[(rl + 8)  * QLD + kk + t]);
            a0[2] = __float_as_uint(Qs[(rl)      * QLD + kk + t + 4]);
            a0[3] = __float_as_uint(Qs[(rl + 8)  * QLD + kk + t + 4]);
            a1[0] = __float_as_uint(Qs[(rl + 16) * QLD + kk + t]);
            a1[1] = __float_as_uint(Qs[(rl + 24) * QLD + kk + t]);
            a1[2] = __float_as_uint(Qs[(rl + 16) * QLD + kk + t + 4]);
            a1[3] = __float_as_uint(Qs[(rl + 24) * QLD + kk + t + 4]);
#pragma unroll
            for (int nt = 0; nt < 8; nt++) {
                unsigned bf[2];
                bf[0] = __float_as_uint(Ks[(nt * 8 + g) * QLD + kk + t]);
                bf[1] = __float_as_uint(Ks[(nt * 8 + g) * QLD + kk + t + 4]);
                mma_tf32(sacc[0][nt], a0, bf);
                mma_tf32(sacc[1][nt], a1, bf);
            }
        }

        // RPE bias gather + j-mask
#pragma unroll
        for (int mt = 0; mt < 2; mt++) {
            int r_lo = rl + mt * 16, r_hi = r_lo + 8;
            const unsigned char* b_lo = br[mt * 2];
            const unsigned char* b_hi = br[mt * 2 + 1];
#pragma unroll
            for (int nt = 0; nt < 8; nt++) {
                int j = j0 + nt * 8 + 2 * t;
                if (j < NN) {
                    sacc[mt][nt][0] += Lk[r_lo * 8 + b_lo[j]];
                    sacc[mt][nt][2] += Lk[r_hi * 8 + b_hi[j]];
                } else { sacc[mt][nt][0] = -1e30f; sacc[mt][nt][2] = -1e30f; }
                if (j + 1 < NN) {
                    sacc[mt][nt][1] += Lk[r_lo * 8 + b_lo[j + 1]];
                    sacc[mt][nt][3] += Lk[r_hi * 8 + b_hi[j + 1]];
                } else { sacc[mt][nt][1] = -1e30f; sacc[mt][nt][3] = -1e30f; }
            }
        }

        // online softmax per row-slot (quad-owned rows; shfl xor 1,2)
#pragma unroll
        for (int mt = 0; mt < 2; mt++)
#pragma unroll
            for (int half = 0; half < 2; half++) {
                int s = mt * 2 + half;
                int c0 = half * 2, c1 = c0 + 1;
                float mtv = -1e30f;
#pragma unroll
                for (int nt = 0; nt < 8; nt++)
                    mtv = fmaxf(mtv, fmaxf(sacc[mt][nt][c0], sacc[mt][nt][c1]));
                mtv = fmaxf(mtv, __shfl_xor_sync(0xffffffffu, mtv, 1));
                mtv = fmaxf(mtv, __shfl_xor_sync(0xffffffffu, mtv, 2));
                float mn = fmaxf(mx[s], mtv);
                float al = __expf(mx[s] - mn);
                float sum = 0.f;
                int prow = rl + mt * 16 + half * 8;
#pragma unroll
                for (int nt = 0; nt < 8; nt++) {
                    float p0 = __expf(sacc[mt][nt][c0] - mn);
                    float p1 = __expf(sacc[mt][nt][c1] - mn);
                    sum += p0 + p1;
                    float2 pp;
                    pp.x = f2tff(p0); pp.y = f2tff(p1);
                    *(float2*)(Ps + prow * QLD + nt * 8 + 2 * t) = pp;
                }
                sum += __shfl_xor_sync(0xffffffffu, sum, 1);
                sum += __shfl_xor_sync(0xffffffffu, sum, 2);
                ll[s] = ll[s] * al + sum;
                mx[s] = mn;
#pragma unroll
                for (int nt = 0; nt < 8; nt++) {
                    oacc[mt][nt][c0] *= al;
                    oacc[mt][nt][c1] *= al;
                }
            }
        __syncwarp();   // P rows are warp-local: warp-sync suffices

        // O += P V   (B = V^T[d][j])
#pragma unroll
        for (int ks = 0; ks < 8; ks++) {
            int kk = ks * 8;
            unsigned a0[4], a1[4];
            a0[0] = __float_as_uint(Ps[(rl)      * QLD + kk + t]);
            a0[1] = __float_as_uint(Ps[(rl + 8)  * QLD + kk + t]);
            a0[2] = __float_as_uint(Ps[(rl)      * QLD + kk + t + 4]);
            a0[3] = __float_as_uint(Ps[(rl + 8)  * QLD + kk + t + 4]);
            a1[0] = __float_as_uint(Ps[(rl + 16) * QLD + kk + t]);
            a1[1] = __float_as_uint(Ps[(rl + 24) * QLD + kk + t]);
            a1[2] = __float_as_uint(Ps[(rl + 16) * QLD + kk + t + 4]);
            a1[3] = __float_as_uint(Ps[(rl + 24) * QLD + kk + t + 4]);
#pragma unroll
            for (int nt = 0; nt < 8; nt++) {
                unsigned bf[2];
                bf[0] = __float_as_uint(Vs[(nt * 8 + g) * QLD + kk + t]);
                bf[1] = __float_as_uint(Vs[(nt * 8 + g) * QLD + kk + t + 4]);
                mma_tf32(oacc[0][nt], a0, bf);
                mma_tf32(oacc[1][nt], a1, bf);
            }
        }
        __syncthreads();   // all warps done with Ks/Vs before next prefetch
    }

    // normalize + store
#pragma unroll
    for (int mt = 0; mt < 2; mt++)
#pragma unroll
        for (int half = 0; half < 2; half++) {
            int s = mt * 2 + half;
            int gr = grow[s];
            if (gr < NN) {
                float inv = 1.0f / ll[s];
                int c0 = half * 2;
#pragma unroll
                for (int nt = 0; nt < 8; nt++) {
                    float2 o;
                    o.x = oacc[mt][nt][c0] * inv;
                    o.y = oacc[mt][nt][c0 + 1] * inv;
                    *(float2*)(g_ao + ((size_t)b * NN + gr) * CC + h * HD + nt * 8 + 2 * t) = o;
                }
            }
        }
}

// ---------------- launch ----------------------------------------------------
extern "C" void kernel_launch(void* const* d_in, const int* in_sizes, int n_in,
                              void* d_out, int out_size) {
    (void)in_sizes; (void)n_in; (void)out_size;
    const float* x      = (const float*)d_in[0];
    const float* qkv_w  = (const float*)d_in[1];
    const float* proj_w = (const float*)d_in[2];
    const float* proj_b = (const float*)d_in[3];
    const float* rpe_w  = (const float*)d_in[4];
    float* out = (float*)d_out;

    cudaFuncSetAttribute(flash_mma,
                         cudaFuncAttributeMaxDynamicSharedMemorySize, FLASH_SMEM);

    bucket_kernel<<<(NN * NN + 255) / 256, 256>>>();
    qkv_gemm_t<<<dim3(2304 / 128, (MROWS + 127) / 128), 256>>>(x, qkv_w);
    flash_mma<<<dim3(BH, NQP / 128), 128, FLASH_SMEM>>>(rpe_w);
    proj_gemm_t<<<dim3(CC / 128, (MROWS + 127) / 128), 256>>>(proj_w, proj_b, out);
}

// round 9
// speedup vs baseline: 2.9029x; 1.3201x over previous
#include <cuda_runtime.h>
#include <cuda_fp16.h>
#include <math.h>

#define NN    1025
#define CC    768
#define HH    12
#define HD    64
#define BH    96        // B*H
#define MROWS 8200      // B*N
#define NKV   1088      // 17*64  (kv padding)
#define NQP   1152      // 9*128  (q padding)

// ---------------- scratch (device globals, zero-initialized) ---------------
__device__ __half g_qh[BH * NQP * HD];    // fp16, pre-scaled by 1/8, padded rows = 0
__device__ __half g_kh[BH * NKV * HD];    // fp16, padded rows = 0
__device__ __half g_vth[BH * HD * NKV];   // V transposed [bh][d][j], fp16, padded = 0
__device__ float  g_ao[MROWS * CC];       // attention output, [B,N,C]
__device__ unsigned char g_bucket[NN * NN];

// ---------------- bucket table (static geometry, fp64 to match numpy) ------
__global__ void bucket_kernel() {
    int idx = blockIdx.x * 256 + threadIdx.x;
    if (idx >= NN * NN) return;
    int i = idx / NN, j = idx - (idx / NN) * NN;
    int v;
    if (i == 0 || j == 0) {
        v = 7;
    } else {
        int p = i - 1, q = j - 1;
        int dy = (p >> 5) - (q >> 5);
        int dx = (p & 31) - (q & 31);
        double dis = rint(sqrt((double)(dy * dy + dx * dx)));
        if (dis <= 1.9) {
            v = (int)dis;
        } else {
            double t = rint(1.9 + log(dis / 1.9) / log(8.0) * 1.9);
            if (t > 3.8) t = 3.8;
            v = (int)t;
        }
    }
    g_bucket[idx] = (unsigned char)v;
}

// ---------------- fp16 mma helper ------------------------------------------
__device__ __forceinline__ void mma_f16(float* c, const unsigned* a, const unsigned* b) {
    asm volatile(
        "mma.sync.aligned.m16n8k16.row.col.f32.f16.f16.f32 "
        "{%0,%1,%2,%3}, {%4,%5,%6,%7}, {%8,%9}, {%0,%1,%2,%3};\n"
        : "+f"(c[0]), "+f"(c[1]), "+f"(c[2]), "+f"(c[3])
        : "r"(a[0]), "r"(a[1]), "r"(a[2]), "r"(a[3]), "r"(b[0]), "r"(b[1]));
}

__device__ __forceinline__ unsigned pack_h2(float x, float y) {
    __half2 h = __floats2half2_rn(x, y);
    return *(unsigned*)&h;
}

__device__ __forceinline__ void cp16(void* dst, const void* src) {
    unsigned d = (unsigned)__cvta_generic_to_shared(dst);
    asm volatile("cp.async.cg.shared.global [%0], [%1], 16;" :: "r"(d), "l"(src));
}
#define CP_COMMIT() asm volatile("cp.async.commit_group;")
#define CP_WAIT0()  asm volatile("cp.async.wait_group 0;" ::: "memory")

// ---------------- dense GEMM core (fp16 mma, fp32 acc) ----------------------
// Tile 128x128, BK=32. Smem rows: 40 halves (32 + 8 pad) -> bank = 4g+t perm.
#define TLD2 40

#define GEMM_F16_BODY(APTR, AGUARD)                                            \
    __shared__ __half As[128][TLD2];                                           \
    __shared__ __half Bs[128][TLD2];                                           \
    int tid = threadIdx.x;                                                     \
    int lane = tid & 31, wid = tid >> 5;                                       \
    int wm = wid & 1, wn = wid >> 1;                                           \
    int g = lane >> 2, t = lane & 3;                                           \
    int m0 = blockIdx.y * 128, n0 = blockIdx.x * 128;                          \
    float acc[4][4][4];                                                        \
    _Pragma("unroll") for (int mt = 0; mt < 4; mt++)                           \
    _Pragma("unroll") for (int nt = 0; nt < 4; nt++)                           \
    _Pragma("unroll") for (int i = 0; i < 4; i++) acc[mt][nt][i] = 0.f;        \
    int lr = tid >> 3;                                                         \
    int lc = (tid & 7) * 4;                                                    \
    for (int k0 = 0; k0 < CC; k0 += 32) {                                      \
        _Pragma("unroll") for (int p = 0; p < 4; p++) {                        \
            int row = lr + p * 32;                                             \
            int gm = m0 + row;                                                 \
            float4 av = make_float4(0.f, 0.f, 0.f, 0.f);                       \
            if (AGUARD) av = *(const float4*)(APTR + (size_t)gm * CC + k0 + lc);\
            uint2 ap;                                                          \
            ap.x = pack_h2(av.x, av.y); ap.y = pack_h2(av.z, av.w);            \
            *(uint2*)&As[row][lc] = ap;                                        \
            float4 bv = *(const float4*)(W + (size_t)(n0 + row) * CC + k0 + lc);\
            uint2 bp;                                                          \
            bp.x = pack_h2(bv.x, bv.y); bp.y = pack_h2(bv.z, bv.w);            \
            *(uint2*)&Bs[row][lc] = bp;                                        \
        }                                                                      \
        __syncthreads();                                                       \
        _Pragma("unroll") for (int ks = 0; ks < 2; ks++) {                     \
            int kk = ks * 16;                                                  \
            unsigned af[4][4], bf[4][2];                                       \
            _Pragma("unroll") for (int mt = 0; mt < 4; mt++) {                 \
                int rb = wm * 64 + mt * 16;                                    \
                af[mt][0] = *(unsigned*)&As[rb + g][kk + 2 * t];               \
                af[mt][1] = *(unsigned*)&As[rb + g + 8][kk + 2 * t];           \
                af[mt][2] = *(unsigned*)&As[rb + g][kk + 2 * t + 8];           \
                af[mt][3] = *(unsigned*)&As[rb + g + 8][kk + 2 * t + 8];       \
            }                                                                  \
            _Pragma("unroll") for (int nt = 0; nt < 4; nt++) {                 \
                int nb = wn * 32 + nt * 8;                                     \
                bf[nt][0] = *(unsigned*)&Bs[nb + g][kk + 2 * t];               \
                bf[nt][1] = *(unsigned*)&Bs[nb + g][kk + 2 * t + 8];           \
            }                                                                  \
            _Pragma("unroll") for (int mt = 0; mt < 4; mt++)                   \
            _Pragma("unroll") for (int nt = 0; nt < 4; nt++)                   \
                mma_f16(acc[mt][nt], af[mt], bf[nt]);                          \
        }                                                                      \
        __syncthreads();                                                       \
    }

// ---------------- QKV GEMM ---------------------------------------------------
__global__ __launch_bounds__(256) void qkv_gemm_t(const float* __restrict__ X,
                                                  const float* __restrict__ W) {
    GEMM_F16_BODY(X, (gm < MROWS))

#pragma unroll
    for (int mt = 0; mt < 4; mt++) {
#pragma unroll
        for (int half = 0; half < 2; half++) {
            int m = m0 + wm * 64 + mt * 16 + g + half * 8;
            if (m >= MROWS) continue;
            int b = m / NN, i = m - b * NN;
#pragma unroll
            for (int nt = 0; nt < 4; nt++) {
                int n = n0 + wn * 32 + nt * 8 + 2 * t;
                int which = n / CC;
                int cc = n - which * CC;
                int h = cc >> 6, d = cc & 63;
                int bhv = b * HH + h;
                float vx = acc[mt][nt][half * 2 + 0];
                float vy = acc[mt][nt][half * 2 + 1];
                if (which == 0) {
                    unsigned p = pack_h2(vx * 0.125f, vy * 0.125f);
                    *(unsigned*)(g_qh + ((size_t)bhv * NQP + i) * HD + d) = p;
                } else if (which == 1) {
                    unsigned p = pack_h2(vx, vy);
                    *(unsigned*)(g_kh + ((size_t)bhv * NKV + i) * HD + d) = p;
                } else {
                    size_t base = (size_t)bhv * HD;
                    g_vth[(base + d) * NKV + i]     = __float2half_rn(vx);
                    g_vth[(base + d + 1) * NKV + i] = __float2half_rn(vy);
                }
            }
        }
    }
}

// ---------------- proj GEMM --------------------------------------------------
__global__ __launch_bounds__(256) void proj_gemm_t(const float* __restrict__ W,
                                                   const float* __restrict__ bias,
                                                   float* __restrict__ out) {
    const float* A = g_ao;
    GEMM_F16_BODY(A, (gm < MROWS))

#pragma unroll
    for (int mt = 0; mt < 4; mt++) {
#pragma unroll
        for (int half = 0; half < 2; half++) {
            int m = m0 + wm * 64 + mt * 16 + g + half * 8;
            if (m >= MROWS) continue;
#pragma unroll
            for (int nt = 0; nt < 4; nt++) {
                int n = n0 + wn * 32 + nt * 8 + 2 * t;
                float2 v;
                v.x = acc[mt][nt][half * 2 + 0] + bias[n];
                v.y = acc[mt][nt][half * 2 + 1] + bias[n + 1];
                *(float2*)(out + (size_t)m * CC + n) = v;
            }
        }
    }
}

// ---------------- flash attention, fp16 mma, 128-row q-blocks ---------------
// 128 threads = 4 warps; warp w owns 32 q-rows (2 m-tiles). 9 q-blocks per bh.
// Smem rows: 72 halves (64 + 8 pad) -> bank = 4g+t perm for all access patterns.
#define QLD2 72
#define HOF_K (128 * QLD2)
#define HOF_V (HOF_K + 64 * QLD2)
#define HOF_P (HOF_V + 64 * QLD2)
#define HOF_LK (HOF_P + 128 * QLD2)            // float region starts here (halves)
#define FLASH_SMEM (HOF_LK * 2 + 128 * 8 * 4)

__global__ void __launch_bounds__(128, 2) flash_mma(const float* __restrict__ rpe_w) {
    extern __shared__ __half smh[];
    __half* Qs = smh;
    __half* Ks = smh + HOF_K;
    __half* Vs = smh + HOF_V;
    __half* Ps = smh + HOF_P;
    float*  Lk = (float*)(smh + HOF_LK);

    int tid = threadIdx.x;
    int lane = tid & 31, w = tid >> 5;
    int g = lane >> 2, t = lane & 3;
    int bh = blockIdx.x;
    int b = bh / HH, h = bh - b * HH;
    int i0 = blockIdx.y * 128;

    const __half* qb  = g_qh  + (size_t)bh * NQP * HD;
    const __half* kb  = g_kh  + (size_t)bh * NKV * HD;
    const __half* vtb = g_vth + (size_t)bh * HD * NKV;

    // Q tile: 128 rows x 64 halves, 8 chunks of 16B per row
#pragma unroll
    for (int c = 0; c < 8; c++) {
        int ch = tid + c * 128;
        int r = ch >> 3, q = ch & 7;
        cp16(Qs + r * QLD2 + q * 8, qb + (size_t)(i0 + r) * HD + q * 8);
    }
    CP_COMMIT(); CP_WAIT0(); __syncthreads();

    // per-row RPE lookup table: Lk[r][m] = q_r . rpe_w[:,m]
    for (int tq = tid; tq < 1024; tq += 128) {
        int r = tq >> 3, m = tq & 7;
        float s = 0.f;
#pragma unroll
        for (int d = 0; d < HD; d++)
            s += __half2float(Qs[r * QLD2 + d]) * rpe_w[d * 8 + m];
        Lk[r * 8 + m] = s;
    }
    __syncthreads();

    int rl = w * 32 + g;
    int grow[4];
    const unsigned char* br[4];
#pragma unroll
    for (int s = 0; s < 4; s++) {
        int r = i0 + rl + (s >> 1) * 16 + (s & 1) * 8;   // s = mt*2 + half
        grow[s] = r;
        int rc = r < NN ? r : NN - 1;
        br[s] = g_bucket + (size_t)rc * NN;
    }

    float mx[4], ll[4];
#pragma unroll
    for (int s = 0; s < 4; s++) { mx[s] = -1e30f; ll[s] = 0.f; }
    float oacc[2][8][4];
#pragma unroll
    for (int mt = 0; mt < 2; mt++)
#pragma unroll
        for (int nt = 0; nt < 8; nt++)
#pragma unroll
            for (int c = 0; c < 4; c++) oacc[mt][nt][c] = 0.f;

    for (int kt = 0; kt < 17; kt++) {
        int j0 = kt * 64;
        // prefetch K rows + V^T rows (padded, unguarded)
#pragma unroll
        for (int c = 0; c < 4; c++) {
            int ch = tid + c * 128;
            int r = ch >> 3, q = ch & 7;
            cp16(Ks + r * QLD2 + q * 8, kb + (size_t)(j0 + r) * HD + q * 8);
        }
#pragma unroll
        for (int c = 0; c < 4; c++) {
            int ch = tid + c * 128;
            int r = ch >> 3, q = ch & 7;
            cp16(Vs + r * QLD2 + q * 8, vtb + (size_t)r * NKV + j0 + q * 8);
        }
        CP_COMMIT(); CP_WAIT0(); __syncthreads();

        // S = Q K^T, 2 m-tiles per warp, 4 k16 steps
        float sacc[2][8][4];
#pragma unroll
        for (int mt = 0; mt < 2; mt++)
#pragma unroll
            for (int nt = 0; nt < 8; nt++)
#pragma unroll
                for (int c = 0; c < 4; c++) sacc[mt][nt][c] = 0.f;
#pragma unroll
        for (int ks = 0; ks < 4; ks++) {
            int kk = ks * 16;
            unsigned a0[4], a1[4];
            a0[0] = *(unsigned*)&Qs[(rl)      * QLD2 + kk + 2 * t];
            a0[1] = *(unsigned*)&Qs[(rl + 8)  * QLD2 + kk + 2 * t];
            a0[2] = *(unsigned*)&Qs[(rl)      * QLD2 + kk + 2 * t + 8];
            a0[3] = *(unsigned*)&Qs[(rl + 8)  * QLD2 + kk + 2 * t + 8];
            a1[0] = *(unsigned*)&Qs[(rl + 16) * QLD2 + kk + 2 * t];
            a1[1] = *(unsigned*)&Qs[(rl + 24) * QLD2 + kk + 2 * t];
            a1[2] = *(unsigned*)&Qs[(rl + 16) * QLD2 + kk + 2 * t + 8];
            a1[3] = *(unsigned*)&Qs[(rl + 24) * QLD2 + kk + 2 * t + 8];
#pragma unroll
            for (int nt = 0; nt < 8; nt++) {
                unsigned bf[2];
                bf[0] = *(unsigned*)&Ks[(nt * 8 + g) * QLD2 + kk + 2 * t];
                bf[1] = *(unsigned*)&Ks[(nt * 8 + g) * QLD2 + kk + 2 * t + 8];
                mma_f16(sacc[0][nt], a0, bf);
                mma_f16(sacc[1][nt], a1, bf);
            }
        }

        // RPE bias gather + j-mask
#pragma unroll
        for (int mt = 0; mt < 2; mt++) {
            int r_lo = rl + mt * 16, r_hi = r_lo + 8;
            const unsigned char* b_lo = br[mt * 2];
            const unsigned char* b_hi = br[mt * 2 + 1];
#pragma unroll
            for (int nt = 0; nt < 8; nt++) {
                int j = j0 + nt * 8 + 2 * t;
                if (j < NN) {
                    sacc[mt][nt][0] += Lk[r_lo * 8 + b_lo[j]];
                    sacc[mt][nt][2] += Lk[r_hi * 8 + b_hi[j]];
                } else { sacc[mt][nt][0] = -1e30f; sacc[mt][nt][2] = -1e30f; }
                if (j + 1 < NN) {
                    sacc[mt][nt][1] += Lk[r_lo * 8 + b_lo[j + 1]];
                    sacc[mt][nt][3] += Lk[r_hi * 8 + b_hi[j + 1]];
                } else { sacc[mt][nt][1] = -1e30f; sacc[mt][nt][3] = -1e30f; }
            }
        }

        // online softmax per row-slot (quad-owned rows; shfl xor 1,2)
#pragma unroll
        for (int mt = 0; mt < 2; mt++)
#pragma unroll
            for (int half = 0; half < 2; half++) {
                int s = mt * 2 + half;
                int c0 = half * 2, c1 = c0 + 1;
                float mtv = -1e30f;
#pragma unroll
                for (int nt = 0; nt < 8; nt++)
                    mtv = fmaxf(mtv, fmaxf(sacc[mt][nt][c0], sacc[mt][nt][c1]));
                mtv = fmaxf(mtv, __shfl_xor_sync(0xffffffffu, mtv, 1));
                mtv = fmaxf(mtv, __shfl_xor_sync(0xffffffffu, mtv, 2));
                float mn = fmaxf(mx[s], mtv);
                float al = __expf(mx[s] - mn);
                float sum = 0.f;
                int prow = rl + mt * 16 + half * 8;
#pragma unroll
                for (int nt = 0; nt < 8; nt++) {
                    float p0 = __expf(sacc[mt][nt][c0] - mn);
                    float p1 = __expf(sacc[mt][nt][c1] - mn);
                    sum += p0 + p1;
                    *(unsigned*)(Ps + prow * QLD2 + nt * 8 + 2 * t) = pack_h2(p0, p1);
                }
                sum += __shfl_xor_sync(0xffffffffu, sum, 1);
                sum += __shfl_xor_sync(0xffffffffu, sum, 2);
                ll[s] = ll[s] * al + sum;
                mx[s] = mn;
#pragma unroll
                for (int nt = 0; nt < 8; nt++) {
                    oacc[mt][nt][c0] *= al;
                    oacc[mt][nt][c1] *= al;
                }
            }
        __syncwarp();   // P rows are warp-local

        // O += P V   (B = V^T[d][j]), 4 k16 steps over j
#pragma unroll
        for (int ks = 0; ks < 4; ks++) {
            int kk = ks * 16;
            unsigned a0[4], a1[4];
            a0[0] = *(unsigned*)&Ps[(rl)      * QLD2 + kk + 2 * t];
            a0[1] = *(unsigned*)&Ps[(rl + 8)  * QLD2 + kk + 2 * t];
            a0[2] = *(unsigned*)&Ps[(rl)      * QLD2 + kk + 2 * t + 8];
            a0[3] = *(unsigned*)&Ps[(rl + 8)  * QLD2 + kk + 2 * t + 8];
            a1[0] = *(unsigned*)&Ps[(rl + 16) * QLD2 + kk + 2 * t];
            a1[1] = *(unsigned*)&Ps[(rl + 24) * QLD2 + kk + 2 * t];
            a1[2] = *(unsigned*)&Ps[(rl + 16) * QLD2 + kk + 2 * t + 8];
            a1[3] = *(unsigned*)&Ps[(rl + 24) * QLD2 + kk + 2 * t + 8];
#pragma unroll
            for (int nt = 0; nt < 8; nt++) {
                unsigned bf[2];
                bf[0] = *(unsigned*)&Vs[(nt * 8 + g) * QLD2 + kk + 2 * t];
                bf[1] = *(unsigned*)&Vs[(nt * 8 + g) * QLD2 + kk + 2 * t + 8];
                mma_f16(oacc[0][nt], a0, bf);
                mma_f16(oacc[1][nt], a1, bf);
            }
        }
        __syncthreads();   // all warps done with Ks/Vs before next prefetch
    }

    // normalize + store
#pragma unroll
    for (int mt = 0; mt < 2; mt++)
#pragma unroll
        for (int half = 0; half < 2; half++) {
            int s = mt * 2 + half;
            int gr = grow[s];
            if (gr < NN) {
                float inv = 1.0f / ll[s];
                int c0 = half * 2;
#pragma unroll
                for (int nt = 0; nt < 8; nt++) {
                    float2 o;
                    o.x = oacc[mt][nt][c0] * inv;
                    o.y = oacc[mt][nt][c0 + 1] * inv;
                    *(float2*)(g_ao + ((size_t)b * NN + gr) * CC + h * HD + nt * 8 + 2 * t) = o;
                }
            }
        }
}

// ---------------- launch ----------------------------------------------------
extern "C" void kernel_launch(void* const* d_in, const int* in_sizes, int n_in,
                              void* d_out, int out_size) {
    (void)in_sizes; (void)n_in; (void)out_size;
    const float* x      = (const float*)d_in[0];
    const float* qkv_w  = (const float*)d_in[1];
    const float* proj_w = (const float*)d_in[2];
    const float* proj_b = (const float*)d_in[3];
    const float* rpe_w  = (const float*)d_in[4];
    float* out = (float*)d_out;

    cudaFuncSetAttribute(flash_mma,
                         cudaFuncAttributeMaxDynamicSharedMemorySize, FLASH_SMEM);

    bucket_kernel<<<(NN * NN + 255) / 256, 256>>>();
    qkv_gemm_t<<<dim3(2304 / 128, (MROWS + 127) / 128), 256>>>(x, qkv_w);
    flash_mma<<<dim3(BH, NQP / 128), 128, FLASH_SMEM>>>(rpe_w);
    proj_gemm_t<<<dim3(CC / 128, (MROWS + 127) / 128), 256>>>(proj_w, proj_b, out);
}

// round 10
// speedup vs baseline: 3.3285x; 1.1466x over previous
#include <cuda_runtime.h>
#include <cuda_fp16.h>
#include <math.h>

#define NN    1025
#define CC    768
#define HH    12
#define HD    64
#define BH    96        // B*H
#define MROWS 8200      // B*N
#define NKV   1088      // 17*64  (kv padding)
#define NQP   1152      // 9*128  (q padding)

// ---------------- scratch (device globals, zero-initialized) ---------------
__device__ __half g_xh[MROWS * CC];       // x converted to fp16
__device__ __half g_wqh[3 * CC * CC];     // qkv_w fp16
__device__ __half g_wph[CC * CC];         // proj_w fp16
__device__ __half g_qh[BH * NQP * HD];    // fp16, pre-scaled by 1/8, padded rows = 0
__device__ __half g_kh[BH * NKV * HD];    // fp16, padded rows = 0
__device__ __half g_vth[BH * HD * NKV];   // V transposed [bh][d][j], fp16, padded = 0
__device__ __half g_aoh[MROWS * CC];      // attention output fp16, [B,N,C]
__device__ unsigned char g_bucket[NN * NN];

// ---------------- bucket table (static geometry, fp64 to match numpy) ------
__global__ void bucket_kernel() {
    int idx = blockIdx.x * 256 + threadIdx.x;
    if (idx >= NN * NN) return;
    int i = idx / NN, j = idx - (idx / NN) * NN;
    int v;
    if (i == 0 || j == 0) {
        v = 7;
    } else {
        int p = i - 1, q = j - 1;
        int dy = (p >> 5) - (q >> 5);
        int dx = (p & 31) - (q & 31);
        double dis = rint(sqrt((double)(dy * dy + dx * dx)));
        if (dis <= 1.9) {
            v = (int)dis;
        } else {
            double t = rint(1.9 + log(dis / 1.9) / log(8.0) * 1.9);
            if (t > 3.8) t = 3.8;
            v = (int)t;
        }
    }
    g_bucket[idx] = (unsigned char)v;
}

// ---------------- helpers ---------------------------------------------------
__device__ __forceinline__ void mma_f16(float* c, const unsigned* a, const unsigned* b) {
    asm volatile(
        "mma.sync.aligned.m16n8k16.row.col.f32.f16.f16.f32 "
        "{%0,%1,%2,%3}, {%4,%5,%6,%7}, {%8,%9}, {%0,%1,%2,%3};\n"
        : "+f"(c[0]), "+f"(c[1]), "+f"(c[2]), "+f"(c[3])
        : "r"(a[0]), "r"(a[1]), "r"(a[2]), "r"(a[3]), "r"(b[0]), "r"(b[1]));
}

__device__ __forceinline__ unsigned pack_h2(float x, float y) {
    __half2 h = __floats2half2_rn(x, y);
    return *(unsigned*)&h;
}

__device__ __forceinline__ void cp16(void* dst, const void* src) {
    unsigned d = (unsigned)__cvta_generic_to_shared(dst);
    asm volatile("cp.async.cg.shared.global [%0], [%1], 16;" :: "r"(d), "l"(src));
}
#define CP_COMMIT() asm volatile("cp.async.commit_group;")
#define CP_WAIT0()  asm volatile("cp.async.wait_group 0;" ::: "memory")
#define CP_WAIT1()  asm volatile("cp.async.wait_group 1;" ::: "memory")
#define CP_WAIT2()  asm volatile("cp.async.wait_group 2;" ::: "memory")

// fp32 -> fp16 conversion (vectorized, n % 4 == 0)
__global__ void cvt_kernel(const float* __restrict__ src, __half* __restrict__ dst, int n) {
    int i = (blockIdx.x * 256 + threadIdx.x) * 4;
    if (i < n) {
        float4 v = *(const float4*)(src + i);
        uint2 p;
        p.x = pack_h2(v.x, v.y);
        p.y = pack_h2(v.z, v.w);
        *(uint2*)(dst + i) = p;
    }
}

// ---------------- dense GEMM core: fp16 in gmem, cp.async 2-stage -----------
// Tile 128x128, BK=32. Smem rows: 40 halves (80B = 5*16B, so 16B-aligned chunks).
#define TLD2 40
#define GNT  24   // 768/32 k-tiles

#define GEMM_LOAD(DSTA, DSTB, APTR, BPTR, S, K0)                               \
    _Pragma("unroll") for (int c = 0; c < 2; c++) {                            \
        int ch = tid + c * 256;                                                \
        int row = ch >> 2, q = (ch & 3) * 8;                                   \
        int gm = m0 + row; if (gm >= MROWS) gm = MROWS - 1;                    \
        cp16(&DSTA[S][row][q], APTR + (size_t)gm * CC + (K0) + q);             \
        cp16(&DSTB[S][row][q], BPTR + (size_t)(n0 + row) * CC + (K0) + q);     \
    }

#define GEMM_F16_BODY(APTR, BPTR)                                              \
    __shared__ __half As[2][128][TLD2];                                        \
    __shared__ __half Bs[2][128][TLD2];                                        \
    int tid = threadIdx.x;                                                     \
    int lane = tid & 31, wid = tid >> 5;                                       \
    int wm = wid & 1, wn = wid >> 1;                                           \
    int g = lane >> 2, t = lane & 3;                                           \
    int m0 = blockIdx.y * 128, n0 = blockIdx.x * 128;                          \
    float acc[4][4][4];                                                        \
    _Pragma("unroll") for (int mt = 0; mt < 4; mt++)                           \
    _Pragma("unroll") for (int nt = 0; nt < 4; nt++)                           \
    _Pragma("unroll") for (int i = 0; i < 4; i++) acc[mt][nt][i] = 0.f;        \
    GEMM_LOAD(As, Bs, APTR, BPTR, 0, 0) CP_COMMIT();                           \
    GEMM_LOAD(As, Bs, APTR, BPTR, 1, 32) CP_COMMIT();                          \
    for (int it = 0; it < GNT; it++) {                                         \
        CP_WAIT1(); __syncthreads();                                           \
        int bi = it & 1;                                                       \
        _Pragma("unroll") for (int ks = 0; ks < 2; ks++) {                     \
            int kk = ks * 16;                                                  \
            unsigned af[4][4], bf[4][2];                                       \
            _Pragma("unroll") for (int mt = 0; mt < 4; mt++) {                 \
                int rb = wm * 64 + mt * 16;                                    \
                af[mt][0] = *(unsigned*)&As[bi][rb + g][kk + 2 * t];           \
                af[mt][1] = *(unsigned*)&As[bi][rb + g + 8][kk + 2 * t];       \
                af[mt][2] = *(unsigned*)&As[bi][rb + g][kk + 2 * t + 8];       \
                af[mt][3] = *(unsigned*)&As[bi][rb + g + 8][kk + 2 * t + 8];   \
            }                                                                  \
            _Pragma("unroll") for (int nt = 0; nt < 4; nt++) {                 \
                int nb = wn * 32 + nt * 8;                                     \
                bf[nt][0] = *(unsigned*)&Bs[bi][nb + g][kk + 2 * t];           \
                bf[nt][1] = *(unsigned*)&Bs[bi][nb + g][kk + 2 * t + 8];       \
            }                                                                  \
            _Pragma("unroll") for (int mt = 0; mt < 4; mt++)                   \
            _Pragma("unroll") for (int nt = 0; nt < 4; nt++)                   \
                mma_f16(acc[mt][nt], af[mt], bf[nt]);                          \
        }                                                                      \
        __syncthreads();                                                       \
        if (it + 2 < GNT) { GEMM_LOAD(As, Bs, APTR, BPTR, bi, (it + 2) * 32) } \
        CP_COMMIT();                                                           \
    }

// ---------------- QKV GEMM ---------------------------------------------------
__global__ __launch_bounds__(256) void qkv_gemm_t() {
    const __half* Ap = g_xh;
    const __half* Bp = g_wqh;
    GEMM_F16_BODY(Ap, Bp)

#pragma unroll
    for (int mt = 0; mt < 4; mt++) {
#pragma unroll
        for (int half = 0; half < 2; half++) {
            int m = m0 + wm * 64 + mt * 16 + g + half * 8;
            if (m >= MROWS) continue;
            int b = m / NN, i = m - b * NN;
#pragma unroll
            for (int nt = 0; nt < 4; nt++) {
                int n = n0 + wn * 32 + nt * 8 + 2 * t;
                int which = n / CC;
                int cc = n - which * CC;
                int h = cc >> 6, d = cc & 63;
                int bhv = b * HH + h;
                float vx = acc[mt][nt][half * 2 + 0];
                float vy = acc[mt][nt][half * 2 + 1];
                if (which == 0) {
                    unsigned p = pack_h2(vx * 0.125f, vy * 0.125f);
                    *(unsigned*)(g_qh + ((size_t)bhv * NQP + i) * HD + d) = p;
                } else if (which == 1) {
                    unsigned p = pack_h2(vx, vy);
                    *(unsigned*)(g_kh + ((size_t)bhv * NKV + i) * HD + d) = p;
                } else {
                    size_t base = (size_t)bhv * HD;
                    g_vth[(base + d) * NKV + i]     = __float2half_rn(vx);
                    g_vth[(base + d + 1) * NKV + i] = __float2half_rn(vy);
                }
            }
        }
    }
}

// ---------------- proj GEMM --------------------------------------------------
__global__ __launch_bounds__(256) void proj_gemm_t(const float* __restrict__ bias,
                                                   float* __restrict__ out) {
    const __half* Ap = g_aoh;
    const __half* Bp = g_wph;
    GEMM_F16_BODY(Ap, Bp)

#pragma unroll
    for (int mt = 0; mt < 4; mt++) {
#pragma unroll
        for (int half = 0; half < 2; half++) {
            int m = m0 + wm * 64 + mt * 16 + g + half * 8;
            if (m >= MROWS) continue;
#pragma unroll
            for (int nt = 0; nt < 4; nt++) {
                int n = n0 + wn * 32 + nt * 8 + 2 * t;
                float2 v;
                v.x = acc[mt][nt][half * 2 + 0] + bias[n];
                v.y = acc[mt][nt][half * 2 + 1] + bias[n + 1];
                *(float2*)(out + (size_t)m * CC + n) = v;
            }
        }
    }
}

// ---------------- flash attention, fp16 mma, double-buffered K/V ------------
// 128 threads = 4 warps; warp w owns 32 q-rows (2 m-tiles). 9 q-blocks per bh.
#define QLD2 72
#define KVSZ (64 * QLD2)
#define HOF_K (128 * QLD2)
#define HOF_V (HOF_K + 2 * KVSZ)
#define HOF_P (HOF_V + 2 * KVSZ)
#define HOF_LK (HOF_P + 128 * QLD2)            // float region starts here (halves)
#define FLASH_SMEM (HOF_LK * 2 + 128 * 8 * 4)

#define FKV_LOAD(S, KT)                                                        \
    { int jj0 = (KT) * 64;                                                     \
      _Pragma("unroll") for (int c = 0; c < 4; c++) {                          \
          int ch = tid + c * 128;                                              \
          int r = ch >> 3, q = (ch & 7) * 8;                                   \
          cp16(Ks + (S) * KVSZ + r * QLD2 + q, kb + (size_t)(jj0 + r) * HD + q); \
          cp16(Vs + (S) * KVSZ + r * QLD2 + q, vtb + (size_t)r * NKV + jj0 + q); \
      } }

__global__ void __launch_bounds__(128, 2) flash_mma(const float* __restrict__ rpe_w) {
    extern __shared__ __half smh[];
    __half* Qs = smh;
    __half* Ks = smh + HOF_K;
    __half* Vs = smh + HOF_V;
    __half* Ps = smh + HOF_P;
    float*  Lk = (float*)(smh + HOF_LK);

    int tid = threadIdx.x;
    int lane = tid & 31, w = tid >> 5;
    int g = lane >> 2, t = lane & 3;
    int bh = blockIdx.x;
    int b = bh / HH, h = bh - b * HH;
    int i0 = blockIdx.y * 128;

    const __half* qb  = g_qh  + (size_t)bh * NQP * HD;
    const __half* kb  = g_kh  + (size_t)bh * NKV * HD;
    const __half* vtb = g_vth + (size_t)bh * HD * NKV;

    // prefetch Q (own group), then KV tiles 0 and 1
#pragma unroll
    for (int c = 0; c < 8; c++) {
        int ch = tid + c * 128;
        int r = ch >> 3, q = (ch & 7) * 8;
        cp16(Qs + r * QLD2 + q, qb + (size_t)(i0 + r) * HD + q);
    }
    CP_COMMIT();
    FKV_LOAD(0, 0) CP_COMMIT();
    FKV_LOAD(1, 1) CP_COMMIT();

    CP_WAIT2(); __syncthreads();   // Q ready

    // per-row RPE lookup table: Lk[r][m] = q_r . rpe_w[:,m]
    for (int tq = tid; tq < 1024; tq += 128) {
        int r = tq >> 3, m = tq & 7;
        float s = 0.f;
#pragma unroll
        for (int d = 0; d < HD; d++)
            s += __half2float(Qs[r * QLD2 + d]) * rpe_w[d * 8 + m];
        Lk[r * 8 + m] = s;
    }
    __syncthreads();

    int rl = w * 32 + g;
    int grow[4];
    const unsigned char* br[4];
#pragma unroll
    for (int s = 0; s < 4; s++) {
        int r = i0 + rl + (s >> 1) * 16 + (s & 1) * 8;   // s = mt*2 + half
        grow[s] = r;
        int rc = r < NN ? r : NN - 1;
        br[s] = g_bucket + (size_t)rc * NN;
    }

    float mx[4], ll[4];
#pragma unroll
    for (int s = 0; s < 4; s++) { mx[s] = -1e30f; ll[s] = 0.f; }
    float oacc[2][8][4];
#pragma unroll
    for (int mt = 0; mt < 2; mt++)
#pragma unroll
        for (int nt = 0; nt < 8; nt++)
#pragma unroll
            for (int c = 0; c < 4; c++) oacc[mt][nt][c] = 0.f;

    for (int kt = 0; kt < 17; kt++) {
        int j0 = kt * 64;
        CP_WAIT1(); __syncthreads();     // KV(kt) resident
        int bi = kt & 1;
        const __half* Kb = Ks + bi * KVSZ;
        const __half* Vb = Vs + bi * KVSZ;

        // S = Q K^T, 2 m-tiles per warp, 4 k16 steps
        float sacc[2][8][4];
#pragma unroll
        for (int mt = 0; mt < 2; mt++)
#pragma unroll
            for (int nt = 0; nt < 8; nt++)
#pragma unroll
                for (int c = 0; c < 4; c++) sacc[mt][nt][c] = 0.f;
#pragma unroll
        for (int ks = 0; ks < 4; ks++) {
            int kk = ks * 16;
            unsigned a0[4], a1[4];
            a0[0] = *(unsigned*)&Qs[(rl)      * QLD2 + kk + 2 * t];
            a0[1] = *(unsigned*)&Qs[(rl + 8)  * QLD2 + kk + 2 * t];
            a0[2] = *(unsigned*)&Qs[(rl)      * QLD2 + kk + 2 * t + 8];
            a0[3] = *(unsigned*)&Qs[(rl + 8)  * QLD2 + kk + 2 * t + 8];
            a1[0] = *(unsigned*)&Qs[(rl + 16) * QLD2 + kk + 2 * t];
            a1[1] = *(unsigned*)&Qs[(rl + 24) * QLD2 + kk + 2 * t];
            a1[2] = *(unsigned*)&Qs[(rl + 16) * QLD2 + kk + 2 * t + 8];
            a1[3] = *(unsigned*)&Qs[(rl + 24) * QLD2 + kk + 2 * t + 8];
#pragma unroll
            for (int nt = 0; nt < 8; nt++) {
                unsigned bf[2];
                bf[0] = *(unsigned*)&Kb[(nt * 8 + g) * QLD2 + kk + 2 * t];
                bf[1] = *(unsigned*)&Kb[(nt * 8 + g) * QLD2 + kk + 2 * t + 8];
                mma_f16(sacc[0][nt], a0, bf);
                mma_f16(sacc[1][nt], a1, bf);
            }
        }

        // RPE bias gather + j-mask
#pragma unroll
        for (int mt = 0; mt < 2; mt++) {
            int r_lo = rl + mt * 16, r_hi = r_lo + 8;
            const unsigned char* b_lo = br[mt * 2];
            const unsigned char* b_hi = br[mt * 2 + 1];
#pragma unroll
            for (int nt = 0; nt < 8; nt++) {
                int j = j0 + nt * 8 + 2 * t;
                if (j < NN) {
                    sacc[mt][nt][0] += Lk[r_lo * 8 + b_lo[j]];
                    sacc[mt][nt][2] += Lk[r_hi * 8 + b_hi[j]];
                } else { sacc[mt][nt][0] = -1e30f; sacc[mt][nt][2] = -1e30f; }
                if (j + 1 < NN) {
                    sacc[mt][nt][1] += Lk[r_lo * 8 + b_lo[j + 1]];
                    sacc[mt][nt][3] += Lk[r_hi * 8 + b_hi[j + 1]];
                } else { sacc[mt][nt][1] = -1e30f; sacc[mt][nt][3] = -1e30f; }
            }
        }

        // online softmax per row-slot (quad-owned rows; shfl xor 1,2)
#pragma unroll
        for (int mt = 0; mt < 2; mt++)
#pragma unroll
            for (int half = 0; half < 2; half++) {
                int s = mt * 2 + half;
                int c0 = half * 2, c1 = c0 + 1;
                float mtv = -1e30f;
#pragma unroll
                for (int nt = 0; nt < 8; nt++)
                    mtv = fmaxf(mtv, fmaxf(sacc[mt][nt][c0], sacc[mt][nt][c1]));
                mtv = fmaxf(mtv, __shfl_xor_sync(0xffffffffu, mtv, 1));
                mtv = fmaxf(mtv, __shfl_xor_sync(0xffffffffu, mtv, 2));
                float mn = fmaxf(mx[s], mtv);
                float al = __expf(mx[s] - mn);
                float sum = 0.f;
                int prow = rl + mt * 16 + half * 8;
#pragma unroll
                for (int nt = 0; nt < 8; nt++) {
                    float p0 = __expf(sacc[mt][nt][c0] - mn);
                    float p1 = __expf(sacc[mt][nt][c1] - mn);
                    sum += p0 + p1;
                    *(unsigned*)(Ps + prow * QLD2 + nt * 8 + 2 * t) = pack_h2(p0, p1);
                }
                sum += __shfl_xor_sync(0xffffffffu, sum, 1);
                sum += __shfl_xor_sync(0xffffffffu, sum, 2);
                ll[s] = ll[s] * al + sum;
                mx[s] = mn;
#pragma unroll
                for (int nt = 0; nt < 8; nt++) {
                    oacc[mt][nt][c0] *= al;
                    oacc[mt][nt][c1] *= al;
                }
            }
        __syncwarp();   // P rows are warp-local

        // O += P V   (B = V^T[d][j]), 4 k16 steps over j
#pragma unroll
        for (int ks = 0; ks < 4; ks++) {
            int kk = ks * 16;
            unsigned a0[4], a1[4];
            a0[0] = *(unsigned*)&Ps[(rl)      * QLD2 + kk + 2 * t];
            a0[1] = *(unsigned*)&Ps[(rl + 8)  * QLD2 + kk + 2 * t];
            a0[2] = *(unsigned*)&Ps[(rl)      * QLD2 + kk + 2 * t + 8];
            a0[3] = *(unsigned*)&Ps[(rl + 8)  * QLD2 + kk + 2 * t + 8];
            a1[0] = *(unsigned*)&Ps[(rl + 16) * QLD2 + kk + 2 * t];
            a1[1] = *(unsigned*)&Ps[(rl + 24) * QLD2 + kk + 2 * t];
            a1[2] = *(unsigned*)&Ps[(rl + 16) * QLD2 + kk + 2 * t + 8];
            a1[3] = *(unsigned*)&Ps[(rl + 24) * QLD2 + kk + 2 * t + 8];
#pragma unroll
            for (int nt = 0; nt < 8; nt++) {
                unsigned bf[2];
                bf[0] = *(unsigned*)&Vb[(nt * 8 + g) * QLD2 + kk + 2 * t];
                bf[1] = *(unsigned*)&Vb[(nt * 8 + g) * QLD2 + kk + 2 * t + 8];
                mma_f16(oacc[0][nt], a0, bf);
                mma_f16(oacc[1][nt], a1, bf);
            }
        }
        __syncthreads();               // all warps done with KV(kt) buffer
        if (kt + 2 < 17) { FKV_LOAD(bi, kt + 2) }
        CP_COMMIT();                   // always commit to keep group count uniform
    }

    // normalize + store (fp16 — proj consumes half anyway)
#pragma unroll
    for (int mt = 0; mt < 2; mt++)
#pragma unroll
        for (int half = 0; half < 2; half++) {
            int s = mt * 2 + half;
            int gr = grow[s];
            if (gr < NN) {
                float inv = 1.0f / ll[s];
                int c0 = half * 2;
#pragma unroll
                for (int nt = 0; nt < 8; nt++) {
                    unsigned p = pack_h2(oacc[mt][nt][c0] * inv,
                                         oacc[mt][nt][c0 + 1] * inv);
                    *(unsigned*)(g_aoh + ((size_t)b * NN + gr) * CC + h * HD + nt * 8 + 2 * t) = p;
                }
            }
        }
}

// ---------------- launch ----------------------------------------------------
extern "C" void kernel_launch(void* const* d_in, const int* in_sizes, int n_in,
                              void* d_out, int out_size) {
    (void)in_sizes; (void)n_in; (void)out_size;
    const float* x      = (const float*)d_in[0];
    const float* qkv_w  = (const float*)d_in[1];
    const float* proj_w = (const float*)d_in[2];
    const float* proj_b = (const float*)d_in[3];
    const float* rpe_w  = (const float*)d_in[4];
    float* out = (float*)d_out;

    cudaFuncSetAttribute(flash_mma,
                         cudaFuncAttributeMaxDynamicSharedMemorySize, FLASH_SMEM);

    bucket_kernel<<<(NN * NN + 255) / 256, 256>>>();

    __half* xh;  cudaGetSymbolAddress((void**)&xh,  g_xh);
    __half* wqh; cudaGetSymbolAddress((void**)&wqh, g_wqh);
    __half* wph; cudaGetSymbolAddress((void**)&wph, g_wph);
    cvt_kernel<<<(MROWS * CC / 4 + 255) / 256, 256>>>(x, xh, MROWS * CC);
    cvt_kernel<<<(3 * CC * CC / 4 + 255) / 256, 256>>>(qkv_w, wqh, 3 * CC * CC);
    cvt_kernel<<<(CC * CC / 4 + 255) / 256, 256>>>(proj_w, wph, CC * CC);

    qkv_gemm_t<<<dim3(2304 / 128, (MROWS + 127) / 128), 256>>>();
    flash_mma<<<dim3(BH, NQP / 128), 128, FLASH_SMEM>>>(rpe_w);
    proj_gemm_t<<<dim3(CC / 128, (MROWS + 127) / 128), 256>>>(proj_b, out);
}

// round 15
// speedup vs baseline: 3.6532x; 1.0976x over previous
#include <cuda_runtime.h>
#include <cuda_fp16.h>
#include <math.h>

#define NN    1025
#define CC    768
#define HH    12
#define HD    64
#define BH    96        // B*H
#define MROWS 8200      // B*N
#define NKV   1088      // 17*64  (kv padding)
#define NQP   1152      // 9*128  (q padding)

// ---------------- scratch (device globals, zero-initialized) ---------------
__device__ __half g_xh[MROWS * CC];       // x converted to fp16
__device__ __half g_wqh[3 * CC * CC];     // qkv_w fp16
__device__ __half g_wph[CC * CC];         // proj_w fp16
__device__ __half g_qh[BH * NQP * HD];    // fp16, pre-scaled by 1/8, padded rows = 0
__device__ __half g_kh[BH * NKV * HD];    // fp16, padded rows = 0
__device__ __half g_vth[BH * HD * NKV];   // V transposed [bh][d][j], fp16, padded = 0
__device__ __half g_aoh[MROWS * CC];      // attention output fp16, [B,N,C]
// bucket table padded: 1152 rows x 1088 cols (16B-aligned rows for cp.async)
__device__ __align__(16) unsigned char g_bucket[NQP * NKV];

// ---------------- bucket table (static geometry, fp64 to match numpy) ------
__global__ void bucket_kernel() {
    int idx = blockIdx.x * 256 + threadIdx.x;
    if (idx >= NQP * NKV) return;
    int i = idx / NKV, j = idx - (idx / NKV) * NKV;
    int v;
    if (i >= NN || j >= NN) {
        v = 0;   // padded region (masked later; any valid bucket id)
    } else if (i == 0 || j == 0) {
        v = 7;
    } else {
        int p = i - 1, q = j - 1;
        int dy = (p >> 5) - (q >> 5);
        int dx = (p & 31) - (q & 31);
        double dis = rint(sqrt((double)(dy * dy + dx * dx)));
        if (dis <= 1.9) {
            v = (int)dis;
        } else {
            double t = rint(1.9 + log(dis / 1.9) / log(8.0) * 1.9);
            if (t > 3.8) t = 3.8;
            v = (int)t;
        }
    }
    g_bucket[idx] = (unsigned char)v;
}

// ---------------- helpers ---------------------------------------------------
__device__ __forceinline__ void mma_f16(float* c, const unsigned* a, const unsigned* b) {
    asm volatile(
        "mma.sync.aligned.m16n8k16.row.col.f32.f16.f16.f32 "
        "{%0,%1,%2,%3}, {%4,%5,%6,%7}, {%8,%9}, {%0,%1,%2,%3};\n"
        : "+f"(c[0]), "+f"(c[1]), "+f"(c[2]), "+f"(c[3])
        : "r"(a[0]), "r"(a[1]), "r"(a[2]), "r"(a[3]), "r"(b[0]), "r"(b[1]));
}

__device__ __forceinline__ unsigned pack_h2(float x, float y) {
    __half2 h = __floats2half2_rn(x, y);
    return *(unsigned*)&h;
}

__device__ __forceinline__ void cp16(void* dst, const void* src) {
    unsigned d = (unsigned)__cvta_generic_to_shared(dst);
    asm volatile("cp.async.cg.shared.global [%0], [%1], 16;" :: "r"(d), "l"(src));
}
#define CP_COMMIT() asm volatile("cp.async.commit_group;")
#define CP_WAIT1()  asm volatile("cp.async.wait_group 1;" ::: "memory")
#define CP_WAIT2()  asm volatile("cp.async.wait_group 2;" ::: "memory")

// fp32 -> fp16 conversion (vectorized, n % 4 == 0)
__global__ void cvt_kernel(const float* __restrict__ src, __half* __restrict__ dst, int n) {
    int i = (blockIdx.x * 256 + threadIdx.x) * 4;
    if (i < n) {
        float4 v = *(const float4*)(src + i);
        uint2 p;
        p.x = pack_h2(v.x, v.y);
        p.y = pack_h2(v.z, v.w);
        *(uint2*)(dst + i) = p;
    }
}

// ---------------- dense GEMM core: fp16 in gmem, cp.async 3-stage -----------
// Tile 128x128, BK=32. Smem rows: 40 halves. Dynamic smem: 3 stages A+B = 60KB.
#define TLD2 40
#define GNT  24   // 768/32 k-tiles
#define GEMM_SMEM (3 * 128 * TLD2 * 2 * 2)

#define ASM(S, R, C) gsm[(size_t)(S) * (128 * TLD2) + (R) * TLD2 + (C)]
#define BSM(S, R, C) gsm[3 * 128 * TLD2 + (size_t)(S) * (128 * TLD2) + (R) * TLD2 + (C)]

#define GEMM_LOAD(APTR, BPTR, S, K0)                                           \
    _Pragma("unroll") for (int c = 0; c < 2; c++) {                            \
        int ch = tid + c * 256;                                                \
        int row = ch >> 2, q = (ch & 3) * 8;                                   \
        int gm = m0 + row; if (gm >= MROWS) gm = MROWS - 1;                    \
        cp16(&ASM(S, row, q), APTR + (size_t)gm * CC + (K0) + q);              \
        cp16(&BSM(S, row, q), BPTR + (size_t)(n0 + row) * CC + (K0) + q);      \
    }

#define GEMM_F16_BODY(APTR, BPTR)                                              \
    extern __shared__ __half gsm[];                                            \
    int tid = threadIdx.x;                                                     \
    int lane = tid & 31, wid = tid >> 5;                                       \
    int wm = wid & 1, wn = wid >> 1;                                           \
    int g = lane >> 2, t = lane & 3;                                           \
    int m0 = blockIdx.y * 128, n0 = blockIdx.x * 128;                          \
    float acc[4][4][4];                                                        \
    _Pragma("unroll") for (int mt = 0; mt < 4; mt++)                           \
    _Pragma("unroll") for (int nt = 0; nt < 4; nt++)                           \
    _Pragma("unroll") for (int i = 0; i < 4; i++) acc[mt][nt][i] = 0.f;        \
    GEMM_LOAD(APTR, BPTR, 0, 0)  CP_COMMIT();                                  \
    GEMM_LOAD(APTR, BPTR, 1, 32) CP_COMMIT();                                  \
    GEMM_LOAD(APTR, BPTR, 2, 64) CP_COMMIT();                                  \
    for (int it = 0; it < GNT; it++) {                                         \
        CP_WAIT2(); __syncthreads();                                           \
        int bi = it - (it / 3) * 3;                                            \
        _Pragma("unroll") for (int ks = 0; ks < 2; ks++) {                     \
            int kk = ks * 16;                                                  \
            unsigned af[4][4], bf[4][2];                                       \
            _Pragma("unroll") for (int mt = 0; mt < 4; mt++) {                 \
                int rb = wm * 64 + mt * 16;                                    \
                af[mt][0] = *(unsigned*)&ASM(bi, rb + g, kk + 2 * t);          \
                af[mt][1] = *(unsigned*)&ASM(bi, rb + g + 8, kk + 2 * t);      \
                af[mt][2] = *(unsigned*)&ASM(bi, rb + g, kk + 2 * t + 8);      \
                af[mt][3] = *(unsigned*)&ASM(bi, rb + g + 8, kk + 2 * t + 8);  \
            }                                                                  \
            _Pragma("unroll") for (int nt = 0; nt < 4; nt++) {                 \
                int nb = wn * 32 + nt * 8;                                     \
                bf[nt][0] = *(unsigned*)&BSM(bi, nb + g, kk + 2 * t);          \
                bf[nt][1] = *(unsigned*)&BSM(bi, nb + g, kk + 2 * t + 8);      \
            }                                                                  \
            _Pragma("unroll") for (int mt = 0; mt < 4; mt++)                   \
            _Pragma("unroll") for (int nt = 0; nt < 4; nt++)                   \
                mma_f16(acc[mt][nt], af[mt], bf[nt]);                          \
        }                                                                      \
        __syncthreads();                                                       \
        if (it + 3 < GNT) { GEMM_LOAD(APTR, BPTR, bi, (it + 3) * 32) }         \
        CP_COMMIT();                                                           \
    }

// ---------------- QKV GEMM ---------------------------------------------------
__global__ __launch_bounds__(256) void qkv_gemm_t() {
    const __half* Ap = g_xh;
    const __half* Bp = g_wqh;
    GEMM_F16_BODY(Ap, Bp)

#pragma unroll
    for (int mt = 0; mt < 4; mt++) {
#pragma unroll
        for (int half = 0; half < 2; half++) {
            int m = m0 + wm * 64 + mt * 16 + g + half * 8;
            if (m >= MROWS) continue;
            int b = m / NN, i = m - b * NN;
#pragma unroll
            for (int nt = 0; nt < 4; nt++) {
                int n = n0 + wn * 32 + nt * 8 + 2 * t;
                int which = n / CC;
                int cc = n - which * CC;
                int h = cc >> 6, d = cc & 63;
                int bhv = b * HH + h;
                float vx = acc[mt][nt][half * 2 + 0];
                float vy = acc[mt][nt][half * 2 + 1];
                if (which == 0) {
                    unsigned p = pack_h2(vx * 0.125f, vy * 0.125f);
                    *(unsigned*)(g_qh + ((size_t)bhv * NQP + i) * HD + d) = p;
                } else if (which == 1) {
                    unsigned p = pack_h2(vx, vy);
                    *(unsigned*)(g_kh + ((size_t)bhv * NKV + i) * HD + d) = p;
                } else {
                    size_t base = (size_t)bhv * HD;
                    g_vth[(base + d) * NKV + i]     = __float2half_rn(vx);
                    g_vth[(base + d + 1) * NKV + i] = __float2half_rn(vy);
                }
            }
        }
    }
}

// ---------------- proj GEMM --------------------------------------------------
__global__ __launch_bounds__(256) void proj_gemm_t(const float* __restrict__ bias,
                                                   float* __restrict__ out) {
    const __half* Ap = g_aoh;
    const __half* Bp = g_wph;
    GEMM_F16_BODY(Ap, Bp)

#pragma unroll
    for (int mt = 0; mt < 4; mt++) {
#pragma unroll
        for (int half = 0; half < 2; half++) {
            int m = m0 + wm * 64 + mt * 16 + g + half * 8;
            if (m >= MROWS) continue;
#pragma unroll
            for (int nt = 0; nt < 4; nt++) {
                int n = n0 + wn * 32 + nt * 8 + 2 * t;
                float2 v;
                v.x = acc[mt][nt][half * 2 + 0] + bias[n];
                v.y = acc[mt][nt][half * 2 + 1] + bias[n + 1];
                *(float2*)(out + (size_t)m * CC + n) = v;
            }
        }
    }
}

// ---------------- flash attention, fp16 mma, double-buffered K/V+bucket -----
// 128 threads = 4 warps; warp w owns 32 q-rows (2 m-tiles). 9 q-blocks per bh.
#define QLD2 72
#define KVSZ (64 * QLD2)
#define HOF_K (128 * QLD2)
#define HOF_V (HOF_K + 2 * KVSZ)
#define HOF_P (HOF_V + 2 * KVSZ)
#define HOF_LK (HOF_P + 128 * QLD2)          // float region (halves offset)
#define HOF_BK (HOF_LK + 2048)               // bucket byte region (halves offset)
#define BKSTR 80                             // smem bucket row stride (bytes)
#define BKSZ  (128 * BKSTR)                  // per-stage bucket tile bytes
#define FLASH_SMEM (HOF_BK * 2 + 2 * BKSZ)

#define FKV_LOAD(S, KT)                                                          \
    { int jj0 = (KT) * 64;                                                       \
      _Pragma("unroll") for (int c = 0; c < 4; c++) {                            \
          int ch = tid + c * 128;                                                \
          int r = ch >> 3, q = (ch & 7) * 8;                                     \
          cp16(Ks + (S) * KVSZ + r * QLD2 + q, kb + (size_t)(jj0 + r) * HD + q); \
          cp16(Vs + (S) * KVSZ + r * QLD2 + q, vtb + (size_t)r * NKV + jj0 + q); \
      }                                                                          \
      _Pragma("unroll") for (int c = 0; c < 4; c++) {                            \
          int ch = tid + c * 128;                                                \
          int r = ch >> 2, q = (ch & 3) * 16;                                    \
          cp16(Bkt + (S) * BKSZ + r * BKSTR + q,                                 \
               g_bucket + (size_t)(i0 + r) * NKV + jj0 + q);                     \
      } }

__global__ void __launch_bounds__(128, 2) flash_mma(const float* __restrict__ rpe_w) {
    extern __shared__ __half smh[];
    __half* Qs = smh;
    __half* Ks = smh + HOF_K;
    __half* Vs = smh + HOF_V;
    __half* Ps = smh + HOF_P;
    float*  Lk = (float*)(smh + HOF_LK);
    unsigned char* Bkt = (unsigned char*)(smh + HOF_BK);

    int tid = threadIdx.x;
    int lane = tid & 31, w = tid >> 5;
    int g = lane >> 2, t = lane & 3;
    int bh = blockIdx.x;
    int b = bh / HH, h = bh - b * HH;
    int i0 = blockIdx.y * 128;

    const __half* qb  = g_qh  + (size_t)bh * NQP * HD;
    const __half* kb  = g_kh  + (size_t)bh * NKV * HD;
    const __half* vtb = g_vth + (size_t)bh * HD * NKV;

    // prefetch Q (own group), then KV+bucket tiles 0 and 1
#pragma unroll
    for (int c = 0; c < 8; c++) {
        int ch = tid + c * 128;
        int r = ch >> 3, q = (ch & 7) * 8;
        cp16(Qs + r * QLD2 + q, qb + (size_t)(i0 + r) * HD + q);
    }
    CP_COMMIT();
    FKV_LOAD(0, 0) CP_COMMIT();
    FKV_LOAD(1, 1) CP_COMMIT();

    CP_WAIT2(); __syncthreads();   // Q ready

    // per-row RPE lookup table: Lk[r][m] = q_r . rpe_w[:,m]
    for (int tq = tid; tq < 1024; tq += 128) {
        int r = tq >> 3, m = tq & 7;
        float s = 0.f;
#pragma unroll
        for (int d = 0; d < HD; d++)
            s += __half2float(Qs[r * QLD2 + d]) * rpe_w[d * 8 + m];
        Lk[r * 8 + m] = s;
    }
    __syncthreads();

    int rl = w * 32 + g;
    int grow[4];
#pragma unroll
    for (int s = 0; s < 4; s++)
        grow[s] = i0 + rl + (s >> 1) * 16 + (s & 1) * 8;   // s = mt*2 + half

    float mx[4], ll[4];
#pragma unroll
    for (int s = 0; s < 4; s++) { mx[s] = -1e30f; ll[s] = 0.f; }
    float oacc[2][8][4];
#pragma unroll
    for (int mt = 0; mt < 2; mt++)
#pragma unroll
        for (int nt = 0; nt < 8; nt++)
#pragma unroll
            for (int c = 0; c < 4; c++) oacc[mt][nt][c] = 0.f;

    for (int kt = 0; kt < 17; kt++) {
        int j0 = kt * 64;
        CP_WAIT1(); __syncthreads();     // KV(kt)+bucket resident
        int bi = kt & 1;
        const __half* Kb = Ks + bi * KVSZ;
        const __half* Vb = Vs + bi * KVSZ;
        const unsigned char* Bk = Bkt + bi * BKSZ;

        // S = Q K^T, 2 m-tiles per warp, 4 k16 steps
        float sacc[2][8][4];
#pragma unroll
        for (int mt = 0; mt < 2; mt++)
#pragma unroll
            for (int nt = 0; nt < 8; nt++)
#pragma unroll
                for (int c = 0; c < 4; c++) sacc[mt][nt][c] = 0.f;
#pragma unroll
        for (int ks = 0; ks < 4; ks++) {
            int kk = ks * 16;
            unsigned a0[4], a1[4];
            a0[0] = *(unsigned*)&Qs[(rl)      * QLD2 + kk + 2 * t];
            a0[1] = *(unsigned*)&Qs[(rl + 8)  * QLD2 + kk + 2 * t];
            a0[2] = *(unsigned*)&Qs[(rl)      * QLD2 + kk + 2 * t + 8];
            a0[3] = *(unsigned*)&Qs[(rl + 8)  * QLD2 + kk + 2 * t + 8];
            a1[0] = *(unsigned*)&Qs[(rl + 16) * QLD2 + kk + 2 * t];
            a1[1] = *(unsigned*)&Qs[(rl + 24) * QLD2 + kk + 2 * t];
            a1[2] = *(unsigned*)&Qs[(rl + 16) * QLD2 + kk + 2 * t + 8];
            a1[3] = *(unsigned*)&Qs[(rl + 24) * QLD2 + kk + 2 * t + 8];
#pragma unroll
            for (int nt = 0; nt < 8; nt++) {
                unsigned bf[2];
                bf[0] = *(unsigned*)&Kb[(nt * 8 + g) * QLD2 + kk + 2 * t];
                bf[1] = *(unsigned*)&Kb[(nt * 8 + g) * QLD2 + kk + 2 * t + 8];
                mma_f16(sacc[0][nt], a0, bf);
                mma_f16(sacc[1][nt], a1, bf);
            }
        }

        // RPE bias gather (bucket from smem) + j-mask
#pragma unroll
        for (int mt = 0; mt < 2; mt++) {
            int r_lo = rl + mt * 16, r_hi = r_lo + 8;
#pragma unroll
            for (int nt = 0; nt < 8; nt++) {
                int jo = nt * 8 + 2 * t;
                int j = j0 + jo;
                unsigned short b_lo = *(const unsigned short*)&Bk[r_lo * BKSTR + jo];
                unsigned short b_hi = *(const unsigned short*)&Bk[r_hi * BKSTR + jo];
                if (j < NN) {
                    sacc[mt][nt][0] += Lk[r_lo * 8 + (b_lo & 0xFF)];
                    sacc[mt][nt][2] += Lk[r_hi * 8 + (b_hi & 0xFF)];
                } else { sacc[mt][nt][0] = -1e30f; sacc[mt][nt][2] = -1e30f; }
                if (j + 1 < NN) {
                    sacc[mt][nt][1] += Lk[r_lo * 8 + (b_lo >> 8)];
                    sacc[mt][nt][3] += Lk[r_hi * 8 + (b_hi >> 8)];
                } else { sacc[mt][nt][1] = -1e30f; sacc[mt][nt][3] = -1e30f; }
            }
        }

        // online softmax per row-slot (quad-owned rows; shfl xor 1,2)
#pragma unroll
        for (int mt = 0; mt < 2; mt++)
#pragma unroll
            for (int half = 0; half < 2; half++) {
                int s = mt * 2 + half;
                int c0 = half * 2, c1 = c0 + 1;
                float mtv = -1e30f;
#pragma unroll
                for (int nt = 0; nt < 8; nt++)
                    mtv = fmaxf(mtv, fmaxf(sacc[mt][nt][c0], sacc[mt][nt][c1]));
                mtv = fmaxf(mtv, __shfl_xor_sync(0xffffffffu, mtv, 1));
                mtv = fmaxf(mtv, __shfl_xor_sync(0xffffffffu, mtv, 2));
                float mn = fmaxf(mx[s], mtv);
                float al = __expf(mx[s] - mn);
                float sum = 0.f;
                int prow = rl + mt * 16 + half * 8;
#pragma unroll
                for (int nt = 0; nt < 8; nt++) {
                    float p0 = __expf(sacc[mt][nt][c0] - mn);
                    float p1 = __expf(sacc[mt][nt][c1] - mn);
                    sum += p0 + p1;
                    *(unsigned*)(Ps + prow * QLD2 + nt * 8 + 2 * t) = pack_h2(p0, p1);
                }
                sum += __shfl_xor_sync(0xffffffffu, sum, 1);
                sum += __shfl_xor_sync(0xffffffffu, sum, 2);
                ll[s] = ll[s] * al + sum;
                mx[s] = mn;
#pragma unroll
                for (int nt = 0; nt < 8; nt++) {
                    oacc[mt][nt][c0] *= al;
                    oacc[mt][nt][c1] *= al;
                }
            }
        __syncwarp();   // P rows are warp-local

        // O += P V   (B = V^T[d][j]), 4 k16 steps over j
#pragma unroll
        for (int ks = 0; ks < 4; ks++) {
            int kk = ks * 16;
            unsigned a0[4], a1[4];
            a0[0] = *(unsigned*)&Ps[(rl)      * QLD2 + kk + 2 * t];
            a0[1] = *(unsigned*)&Ps[(rl + 8)  * QLD2 + kk + 2 * t];
            a0[2] = *(unsigned*)&Ps[(rl)      * QLD2 + kk + 2 * t + 8];
            a0[3] = *(unsigned*)&Ps[(rl + 8)  * QLD2 + kk + 2 * t + 8];
            a1[0] = *(unsigned*)&Ps[(rl + 16) * QLD2 + kk + 2 * t];
            a1[1] = *(unsigned*)&Ps[(rl + 24) * QLD2 + kk + 2 * t];
            a1[2] = *(unsigned*)&Ps[(rl + 16) * QLD2 + kk + 2 * t + 8];
            a1[3] = *(unsigned*)&Ps[(rl + 24) * QLD2 + kk + 2 * t + 8];
#pragma unroll
            for (int nt = 0; nt < 8; nt++) {
                unsigned bf[2];
                bf[0] = *(unsigned*)&Vb[(nt * 8 + g) * QLD2 + kk + 2 * t];
                bf[1] = *(unsigned*)&Vb[(nt * 8 + g) * QLD2 + kk + 2 * t + 8];
                mma_f16(oacc[0][nt], a0, bf);
                mma_f16(oacc[1][nt], a1, bf);
            }
        }
        __syncthreads();               // all warps done with KV(kt) buffer
        if (kt + 2 < 17) { FKV_LOAD(bi, kt + 2) }
        CP_COMMIT();                   // keep group count uniform
    }

    // normalize + store (fp16 — proj consumes half)
#pragma unroll
    for (int mt = 0; mt < 2; mt++)
#pragma unroll
        for (int half = 0; half < 2; half++) {
            int s = mt * 2 + half;
            int gr = grow[s];
            if (gr < NN) {
                float inv = 1.0f / ll[s];
                int c0 = half * 2;
#pragma unroll
                for (int nt = 0; nt < 8; nt++) {
                    unsigned p = pack_h2(oacc[mt][nt][c0] * inv,
                                         oacc[mt][nt][c0 + 1] * inv);
                    *(unsigned*)(g_aoh + ((size_t)b * NN + gr) * CC + h * HD + nt * 8 + 2 * t) = p;
                }
            }
        }
}

// ---------------- launch ----------------------------------------------------
extern "C" void kernel_launch(void* const* d_in, const int* in_sizes, int n_in,
                              void* d_out, int out_size) {
    (void)in_sizes; (void)n_in; (void)out_size;
    const float* x      = (const float*)d_in[0];
    const float* qkv_w  = (const float*)d_in[1];
    const float* proj_w = (const float*)d_in[2];
    const float* proj_b = (const float*)d_in[3];
    const float* rpe_w  = (const float*)d_in[4];
    float* out = (float*)d_out;

    cudaFuncSetAttribute(flash_mma,
                         cudaFuncAttributeMaxDynamicSharedMemorySize, FLASH_SMEM);
    cudaFuncSetAttribute(qkv_gemm_t,
                         cudaFuncAttributeMaxDynamicSharedMemorySize, GEMM_SMEM);
    cudaFuncSetAttribute(proj_gemm_t,
                         cudaFuncAttributeMaxDynamicSharedMemorySize, GEMM_SMEM);

    bucket_kernel<<<(NQP * NKV + 255) / 256, 256>>>();

    __half* xh;  cudaGetSymbolAddress((void**)&xh,  g_xh);
    __half* wqh; cudaGetSymbolAddress((void**)&wqh, g_wqh);
    __half* wph; cudaGetSymbolAddress((void**)&wph, g_wph);
    cvt_kernel<<<(MROWS * CC / 4 + 255) / 256, 256>>>(x, xh, MROWS * CC);
    cvt_kernel<<<(3 * CC * CC / 4 + 255) / 256, 256>>>(qkv_w, wqh, 3 * CC * CC);
    cvt_kernel<<<(CC * CC / 4 + 255) / 256, 256>>>(proj_w, wph, CC * CC);

    qkv_gemm_t<<<dim3(2304 / 128, (MROWS + 127) / 128), 256, GEMM_SMEM>>>();
    flash_mma<<<dim3(BH, NQP / 128), 128, FLASH_SMEM>>>(rpe_w);
    proj_gemm_t<<<dim3(CC / 128, (MROWS + 127) / 128), 256, GEMM_SMEM>>>(proj_b, out);
}

// round 16
// speedup vs baseline: 5.2992x; 1.4506x over previous
#include <cuda_runtime.h>
#include <cuda_fp16.h>
#include <math.h>

#define NN    1025
#define CC    768
#define HH    12
#define HD    64
#define BH    96        // B*H
#define MROWS 8200      // B*N
#define NKV   1088      // 17*64  (kv padding)
#define NQP   1152      // 9*128  (q padding)

// ---------------- scratch (device globals, zero-initialized) ---------------
__device__ __half g_xh[MROWS * CC];       // x converted to fp16
__device__ __half g_wqh[3 * CC * CC];     // qkv_w fp16
__device__ __half g_wph[CC * CC];         // proj_w fp16
__device__ __half g_qh[BH * NQP * HD];    // fp16, pre-scaled by 1/8, padded rows = 0
__device__ __half g_kh[BH * NKV * HD];    // fp16, padded rows = 0
__device__ __half g_vth[BH * HD * NKV];   // V transposed [bh][d][j], fp16, padded = 0
__device__ __half g_aoh[MROWS * CC];      // attention output fp16, [B,N,C]
__device__ __align__(16) unsigned char g_bucket[NQP * NKV];
__device__ unsigned char g_lut[1923];     // bucket by r^2 = dy^2+dx^2

// ---------------- bucket LUT (fp64, 1923 entries) ---------------------------
__global__ void lut_kernel() {
    int r2 = blockIdx.x * 256 + threadIdx.x;
    if (r2 >= 1923) return;
    double dis = rint(sqrt((double)r2));
    int v;
    if (dis <= 1.9) {
        v = (int)dis;
    } else {
        double t = rint(1.9 + log(dis / 1.9) / log(8.0) * 1.9);
        if (t > 3.8) t = 3.8;
        v = (int)t;
    }
    g_lut[r2] = (unsigned char)v;
}

// ---------------- bucket fill (memory-bound, 4 cols per thread) -------------
__global__ void bucket_fill() {
    int idx = blockIdx.x * 256 + threadIdx.x;       // covers NQP * NKV / 4
    if (idx >= NQP * NKV / 4) return;
    int i = idx / (NKV / 4);
    int j4 = (idx - i * (NKV / 4)) * 4;
    uchar4 o;
    unsigned char* po = &o.x;
    if (i >= NN || i == 0) {
        unsigned char v = (i >= NN) ? 0 : 7;
        o.x = o.y = o.z = o.w = v;
        // j==0 col within this quad handled below only when i valid; for i==0 all are 7
        if (i >= NN) { o.x = o.y = o.z = o.w = 0; }
    } else {
        int p = i - 1;
        int py = p >> 5, px = p & 31;
#pragma unroll
        for (int c = 0; c < 4; c++) {
            int j = j4 + c;
            unsigned char v;
            if (j >= NN) v = 0;
            else if (j == 0) v = 7;
            else {
                int q = j - 1;
                int dy = py - (q >> 5), dx = px - (q & 31);
                v = g_lut[dy * dy + dx * dx];
            }
            po[c] = v;
        }
    }
    *(uchar4*)(g_bucket + (size_t)i * NKV + j4) = o;
}

// ---------------- helpers ---------------------------------------------------
__device__ __forceinline__ void mma_f16(float* c, const unsigned* a, const unsigned* b) {
    asm volatile(
        "mma.sync.aligned.m16n8k16.row.col.f32.f16.f16.f32 "
        "{%0,%1,%2,%3}, {%4,%5,%6,%7}, {%8,%9}, {%0,%1,%2,%3};\n"
        : "+f"(c[0]), "+f"(c[1]), "+f"(c[2]), "+f"(c[3])
        : "r"(a[0]), "r"(a[1]), "r"(a[2]), "r"(a[3]), "r"(b[0]), "r"(b[1]));
}

__device__ __forceinline__ unsigned pack_h2(float x, float y) {
    __half2 h = __floats2half2_rn(x, y);
    return *(unsigned*)&h;
}

__device__ __forceinline__ void cp16(void* dst, const void* src) {
    unsigned d = (unsigned)__cvta_generic_to_shared(dst);
    asm volatile("cp.async.cg.shared.global [%0], [%1], 16;" :: "r"(d), "l"(src));
}
#define CP_COMMIT() asm volatile("cp.async.commit_group;")
#define CP_WAIT1()  asm volatile("cp.async.wait_group 1;" ::: "memory")
#define CP_WAIT2()  asm volatile("cp.async.wait_group 2;" ::: "memory")

// ---------------- fused fp32->fp16 conversion (one launch) ------------------
#define CVT_N1 ((size_t)MROWS * CC)
#define CVT_N2 (CVT_N1 + (size_t)3 * CC * CC)
#define CVT_N3 (CVT_N2 + (size_t)CC * CC)

__global__ void cvt_all(const float* __restrict__ x,
                        const float* __restrict__ wq,
                        const float* __restrict__ wp) {
    size_t i = ((size_t)blockIdx.x * 256 + threadIdx.x) * 4;
    if (i >= CVT_N3) return;
    const float* src; __half* dst; size_t off;
    if (i < CVT_N1)      { src = x;  dst = g_xh;  off = i; }
    else if (i < CVT_N2) { src = wq; dst = g_wqh; off = i - CVT_N1; }
    else                 { src = wp; dst = g_wph; off = i - CVT_N2; }
    float4 v = *(const float4*)(src + off);
    uint2 p;
    p.x = pack_h2(v.x, v.y);
    p.y = pack_h2(v.z, v.w);
    *(uint2*)(dst + off) = p;
}

// ---------------- dense GEMM core: fp16 in gmem, cp.async 3-stage -----------
#define TLD2 40
#define GNT  24
#define GEMM_SMEM (3 * 128 * TLD2 * 2 * 2)

#define ASM(S, R, C) gsm[(size_t)(S) * (128 * TLD2) + (R) * TLD2 + (C)]
#define BSM(S, R, C) gsm[3 * 128 * TLD2 + (size_t)(S) * (128 * TLD2) + (R) * TLD2 + (C)]

#define GEMM_LOAD(APTR, BPTR, S, K0)                                           \
    _Pragma("unroll") for (int c = 0; c < 2; c++) {                            \
        int ch = tid + c * 256;                                                \
        int row = ch >> 2, q = (ch & 3) * 8;                                   \
        int gm = m0 + row; if (gm >= MROWS) gm = MROWS - 1;                    \
        cp16(&ASM(S, row, q), APTR + (size_t)gm * CC + (K0) + q);              \
        cp16(&BSM(S, row, q), BPTR + (size_t)(n0 + row) * CC + (K0) + q);      \
    }

#define GEMM_F16_BODY(APTR, BPTR)                                              \
    extern __shared__ __half gsm[];                                            \
    int tid = threadIdx.x;                                                     \
    int lane = tid & 31, wid = tid >> 5;                                       \
    int wm = wid & 1, wn = wid >> 1;                                           \
    int g = lane >> 2, t = lane & 3;                                           \
    int m0 = blockIdx.y * 128, n0 = blockIdx.x * 128;                          \
    float acc[4][4][4];                                                        \
    _Pragma("unroll") for (int mt = 0; mt < 4; mt++)                           \
    _Pragma("unroll") for (int nt = 0; nt < 4; nt++)                           \
    _Pragma("unroll") for (int i = 0; i < 4; i++) acc[mt][nt][i] = 0.f;        \
    GEMM_LOAD(APTR, BPTR, 0, 0)  CP_COMMIT();                                  \
    GEMM_LOAD(APTR, BPTR, 1, 32) CP_COMMIT();                                  \
    GEMM_LOAD(APTR, BPTR, 2, 64) CP_COMMIT();                                  \
    for (int it = 0; it < GNT; it++) {                                         \
        CP_WAIT2(); __syncthreads();                                           \
        int bi = it - (it / 3) * 3;                                            \
        _Pragma("unroll") for (int ks = 0; ks < 2; ks++) {                     \
            int kk = ks * 16;                                                  \
            unsigned af[4][4], bf[4][2];                                       \
            _Pragma("unroll") for (int mt = 0; mt < 4; mt++) {                 \
                int rb = wm * 64 + mt * 16;                                    \
                af[mt][0] = *(unsigned*)&ASM(bi, rb + g, kk + 2 * t);          \
                af[mt][1] = *(unsigned*)&ASM(bi, rb + g + 8, kk + 2 * t);      \
                af[mt][2] = *(unsigned*)&ASM(bi, rb + g, kk + 2 * t + 8);      \
                af[mt][3] = *(unsigned*)&ASM(bi, rb + g + 8, kk + 2 * t + 8);  \
            }                                                                  \
            _Pragma("unroll") for (int nt = 0; nt < 4; nt++) {                 \
                int nb = wn * 32 + nt * 8;                                     \
                bf[nt][0] = *(unsigned*)&BSM(bi, nb + g, kk + 2 * t);          \
                bf[nt][1] = *(unsigned*)&BSM(bi, nb + g, kk + 2 * t + 8);      \
            }                                                                  \
            _Pragma("unroll") for (int mt = 0; mt < 4; mt++)                   \
            _Pragma("unroll") for (int nt = 0; nt < 4; nt++)                   \
                mma_f16(acc[mt][nt], af[mt], bf[nt]);                          \
        }                                                                      \
        __syncthreads();                                                       \
        if (it + 3 < GNT) { GEMM_LOAD(APTR, BPTR, bi, (it + 3) * 32) }         \
        CP_COMMIT();                                                           \
    }

// ---------------- QKV GEMM ---------------------------------------------------
__global__ __launch_bounds__(256) void qkv_gemm_t() {
    const __half* Ap = g_xh;
    const __half* Bp = g_wqh;
    GEMM_F16_BODY(Ap, Bp)

#pragma unroll
    for (int mt = 0; mt < 4; mt++) {
#pragma unroll
        for (int half = 0; half < 2; half++) {
            int m = m0 + wm * 64 + mt * 16 + g + half * 8;
            if (m >= MROWS) continue;
            int b = m / NN, i = m - b * NN;
#pragma unroll
            for (int nt = 0; nt < 4; nt++) {
                int n = n0 + wn * 32 + nt * 8 + 2 * t;
                int which = n / CC;
                int cc = n - which * CC;
                int h = cc >> 6, d = cc & 63;
                int bhv = b * HH + h;
                float vx = acc[mt][nt][half * 2 + 0];
                float vy = acc[mt][nt][half * 2 + 1];
                if (which == 0) {
                    unsigned p = pack_h2(vx * 0.125f, vy * 0.125f);
                    *(unsigned*)(g_qh + ((size_t)bhv * NQP + i) * HD + d) = p;
                } else if (which == 1) {
                    unsigned p = pack_h2(vx, vy);
                    *(unsigned*)(g_kh + ((size_t)bhv * NKV + i) * HD + d) = p;
                } else {
                    size_t base = (size_t)bhv * HD;
                    g_vth[(base + d) * NKV + i]     = __float2half_rn(vx);
                    g_vth[(base + d + 1) * NKV + i] = __float2half_rn(vy);
                }
            }
        }
    }
}

// ---------------- proj GEMM --------------------------------------------------
__global__ __launch_bounds__(256) void proj_gemm_t(const float* __restrict__ bias,
                                                   float* __restrict__ out) {
    const __half* Ap = g_aoh;
    const __half* Bp = g_wph;
    GEMM_F16_BODY(Ap, Bp)

#pragma unroll
    for (int mt = 0; mt < 4; mt++) {
#pragma unroll
        for (int half = 0; half < 2; half++) {
            int m = m0 + wm * 64 + mt * 16 + g + half * 8;
            if (m >= MROWS) continue;
#pragma unroll
            for (int nt = 0; nt < 4; nt++) {
                int n = n0 + wn * 32 + nt * 8 + 2 * t;
                float2 v;
                v.x = acc[mt][nt][half * 2 + 0] + bias[n];
                v.y = acc[mt][nt][half * 2 + 1] + bias[n + 1];
                *(float2*)(out + (size_t)m * CC + n) = v;
            }
        }
    }
}

// ---------------- flash attention: 256 threads, 8 warps, 16 rows/warp -------
#define QLD2 72
#define KVSZ (64 * QLD2)
#define HOF_K (128 * QLD2)
#define HOF_V (HOF_K + 2 * KVSZ)
#define HOF_P (HOF_V + 2 * KVSZ)
#define HOF_LK (HOF_P + 128 * QLD2)          // float region (halves offset)
#define HOF_BK (HOF_LK + 2048)               // bucket byte region (halves offset)
#define BKSTR 80
#define BKSZ  (128 * BKSTR)
#define FLASH_SMEM (HOF_BK * 2 + 2 * BKSZ)

#define FKV_LOAD(S, KT)                                                          \
    { int jj0 = (KT) * 64;                                                       \
      _Pragma("unroll") for (int c = 0; c < 2; c++) {                            \
          int ch = tid + c * 256;                                                \
          int r = ch >> 3, q = (ch & 7) * 8;                                     \
          cp16(Ks + (S) * KVSZ + r * QLD2 + q, kb + (size_t)(jj0 + r) * HD + q); \
          cp16(Vs + (S) * KVSZ + r * QLD2 + q, vtb + (size_t)r * NKV + jj0 + q); \
      }                                                                          \
      _Pragma("unroll") for (int c = 0; c < 2; c++) {                            \
          int ch = tid + c * 256;                                                \
          int r = ch >> 2, q = (ch & 3) * 16;                                    \
          cp16(Bkt + (S) * BKSZ + r * BKSTR + q,                                 \
               g_bucket + (size_t)(i0 + r) * NKV + jj0 + q);                     \
      } }

__global__ void __launch_bounds__(256, 2) flash_mma(const float* __restrict__ rpe_w) {
    extern __shared__ __half smh[];
    __half* Qs = smh;
    __half* Ks = smh + HOF_K;
    __half* Vs = smh + HOF_V;
    __half* Ps = smh + HOF_P;
    float*  Lk = (float*)(smh + HOF_LK);
    unsigned char* Bkt = (unsigned char*)(smh + HOF_BK);

    int tid = threadIdx.x;
    int lane = tid & 31, w = tid >> 5;       // 8 warps
    int g = lane >> 2, t = lane & 3;
    int bh = blockIdx.x;
    int b = bh / HH, h = bh - b * HH;
    int i0 = blockIdx.y * 128;

    const __half* qb  = g_qh  + (size_t)bh * NQP * HD;
    const __half* kb  = g_kh  + (size_t)bh * NKV * HD;
    const __half* vtb = g_vth + (size_t)bh * HD * NKV;

    // prefetch Q (own group), then KV+bucket tiles 0 and 1
#pragma unroll
    for (int c = 0; c < 4; c++) {
        int ch = tid + c * 256;
        int r = ch >> 3, q = (ch & 7) * 8;
        cp16(Qs + r * QLD2 + q, qb + (size_t)(i0 + r) * HD + q);
    }
    CP_COMMIT();
    FKV_LOAD(0, 0) CP_COMMIT();
    FKV_LOAD(1, 1) CP_COMMIT();

    CP_WAIT2(); __syncthreads();   // Q ready

    // per-row RPE lookup table: Lk[r][m] = q_r . rpe_w[:,m]
    for (int tq = tid; tq < 1024; tq += 256) {
        int r = tq >> 3, m = tq & 7;
        float s = 0.f;
#pragma unroll
        for (int d = 0; d < HD; d++)
            s += __half2float(Qs[r * QLD2 + d]) * rpe_w[d * 8 + m];
        Lk[r * 8 + m] = s;
    }
    __syncthreads();

    int rl = w * 16 + g;                     // warp owns rows rl, rl+8
    int grow[2] = { i0 + rl, i0 + rl + 8 };

    float mx[2] = { -1e30f, -1e30f }, ll[2] = { 0.f, 0.f };
    float oacc[8][4];
#pragma unroll
    for (int nt = 0; nt < 8; nt++)
#pragma unroll
        for (int c = 0; c < 4; c++) oacc[nt][c] = 0.f;

    for (int kt = 0; kt < 17; kt++) {
        int j0 = kt * 64;
        CP_WAIT1(); __syncthreads();
        int bi = kt & 1;
        const __half* Kb = Ks + bi * KVSZ;
        const __half* Vb = Vs + bi * KVSZ;
        const unsigned char* Bk = Bkt + bi * BKSZ;

        // S = Q K^T, 1 m-tile per warp, 4 k16 steps
        float sacc[8][4];
#pragma unroll
        for (int nt = 0; nt < 8; nt++)
#pragma unroll
            for (int c = 0; c < 4; c++) sacc[nt][c] = 0.f;
#pragma unroll
        for (int ks = 0; ks < 4; ks++) {
            int kk = ks * 16;
            unsigned a0[4];
            a0[0] = *(unsigned*)&Qs[(rl)     * QLD2 + kk + 2 * t];
            a0[1] = *(unsigned*)&Qs[(rl + 8) * QLD2 + kk + 2 * t];
            a0[2] = *(unsigned*)&Qs[(rl)     * QLD2 + kk + 2 * t + 8];
            a0[3] = *(unsigned*)&Qs[(rl + 8) * QLD2 + kk + 2 * t + 8];
#pragma unroll
            for (int nt = 0; nt < 8; nt++) {
                unsigned bf[2];
                bf[0] = *(unsigned*)&Kb[(nt * 8 + g) * QLD2 + kk + 2 * t];
                bf[1] = *(unsigned*)&Kb[(nt * 8 + g) * QLD2 + kk + 2 * t + 8];
                mma_f16(sacc[nt], a0, bf);
            }
        }

        // RPE bias gather (bucket from smem) + j-mask
        {
            int r_lo = rl, r_hi = rl + 8;
#pragma unroll
            for (int nt = 0; nt < 8; nt++) {
                int jo = nt * 8 + 2 * t;
                int j = j0 + jo;
                unsigned short b_lo = *(const unsigned short*)&Bk[r_lo * BKSTR + jo];
                unsigned short b_hi = *(const unsigned short*)&Bk[r_hi * BKSTR + jo];
                if (j < NN) {
                    sacc[nt][0] += Lk[r_lo * 8 + (b_lo & 0xFF)];
                    sacc[nt][2] += Lk[r_hi * 8 + (b_hi & 0xFF)];
                } else { sacc[nt][0] = -1e30f; sacc[nt][2] = -1e30f; }
                if (j + 1 < NN) {
                    sacc[nt][1] += Lk[r_lo * 8 + (b_lo >> 8)];
                    sacc[nt][3] += Lk[r_hi * 8 + (b_hi >> 8)];
                } else { sacc[nt][1] = -1e30f; sacc[nt][3] = -1e30f; }
            }
        }

        // online softmax per row-slot (quad-owned rows; shfl xor 1,2)
#pragma unroll
        for (int s = 0; s < 2; s++) {
            int c0 = s * 2, c1 = c0 + 1;
            float mtv = -1e30f;
#pragma unroll
            for (int nt = 0; nt < 8; nt++)
                mtv = fmaxf(mtv, fmaxf(sacc[nt][c0], sacc[nt][c1]));
            mtv = fmaxf(mtv, __shfl_xor_sync(0xffffffffu, mtv, 1));
            mtv = fmaxf(mtv, __shfl_xor_sync(0xffffffffu, mtv, 2));
            float mn = fmaxf(mx[s], mtv);
            float al = __expf(mx[s] - mn);
            float sum = 0.f;
            int prow = rl + s * 8;
#pragma unroll
            for (int nt = 0; nt < 8; nt++) {
                float p0 = __expf(sacc[nt][c0] - mn);
                float p1 = __expf(sacc[nt][c1] - mn);
                sum += p0 + p1;
                *(unsigned*)(Ps + prow * QLD2 + nt * 8 + 2 * t) = pack_h2(p0, p1);
            }
            sum += __shfl_xor_sync(0xffffffffu, sum, 1);
            sum += __shfl_xor_sync(0xffffffffu, sum, 2);
            ll[s] = ll[s] * al + sum;
            mx[s] = mn;
#pragma unroll
            for (int nt = 0; nt < 8; nt++) {
                oacc[nt][c0] *= al;
                oacc[nt][c1] *= al;
            }
        }
        __syncwarp();   // P rows are warp-local

        // O += P V   (B = V^T[d][j]), 4 k16 steps over j
#pragma unroll
        for (int ks = 0; ks < 4; ks++) {
            int kk = ks * 16;
            unsigned a0[4];
            a0[0] = *(unsigned*)&Ps[(rl)     * QLD2 + kk + 2 * t];
            a0[1] = *(unsigned*)&Ps[(rl + 8) * QLD2 + kk + 2 * t];
            a0[2] = *(unsigned*)&Ps[(rl)     * QLD2 + kk + 2 * t + 8];
            a0[3] = *(unsigned*)&Ps[(rl + 8) * QLD2 + kk + 2 * t + 8];
#pragma unroll
            for (int nt = 0; nt < 8; nt++) {
                unsigned bf[2];
                bf[0] = *(unsigned*)&Vb[(nt * 8 + g) * QLD2 + kk + 2 * t];
                bf[1] = *(unsigned*)&Vb[(nt * 8 + g) * QLD2 + kk + 2 * t + 8];
                mma_f16(oacc[nt], a0, bf);
            }
        }
        __syncthreads();
        if (kt + 2 < 17) { FKV_LOAD(bi, kt + 2) }
        CP_COMMIT();
    }

    // normalize + store (fp16 — proj consumes half)
#pragma unroll
    for (int s = 0; s < 2; s++) {
        int gr = grow[s];
        if (gr < NN) {
            float inv = 1.0f / ll[s];
            int c0 = s * 2;
#pragma unroll
            for (int nt = 0; nt < 8; nt++) {
                unsigned p = pack_h2(oacc[nt][c0] * inv, oacc[nt][c0 + 1] * inv);
                *(unsigned*)(g_aoh + ((size_t)b * NN + gr) * CC + h * HD + nt * 8 + 2 * t) = p;
            }
        }
    }
}

// ---------------- launch ----------------------------------------------------
extern "C" void kernel_launch(void* const* d_in, const int* in_sizes, int n_in,
                              void* d_out, int out_size) {
    (void)in_sizes; (void)n_in; (void)out_size;
    const float* x      = (const float*)d_in[0];
    const float* qkv_w  = (const float*)d_in[1];
    const float* proj_w = (const float*)d_in[2];
    const float* proj_b = (const float*)d_in[3];
    const float* rpe_w  = (const float*)d_in[4];
    float* out = (float*)d_out;

    cudaFuncSetAttribute(flash_mma,
                         cudaFuncAttributeMaxDynamicSharedMemorySize, FLASH_SMEM);
    cudaFuncSetAttribute(qkv_gemm_t,
                         cudaFuncAttributeMaxDynamicSharedMemorySize, GEMM_SMEM);
    cudaFuncSetAttribute(proj_gemm_t,
                         cudaFuncAttributeMaxDynamicSharedMemorySize, GEMM_SMEM);

    lut_kernel<<<8, 256>>>();
    bucket_fill<<<(NQP * NKV / 4 + 255) / 256, 256>>>();
    cvt_all<<<(unsigned)((CVT_N3 / 4 + 255) / 256), 256>>>(x, qkv_w, proj_w);

    qkv_gemm_t<<<dim3(2304 / 128, (MROWS + 127) / 128), 256, GEMM_SMEM>>>();
    flash_mma<<<dim3(BH, NQP / 128), 256, FLASH_SMEM>>>(rpe_w);
    proj_gemm_t<<<dim3(CC / 128, (MROWS + 127) / 128), 256, GEMM_SMEM>>>(proj_b, out);
}

// round 17
// speedup vs baseline: 5.4229x; 1.0233x over previous
#include <cuda_runtime.h>
#include <cuda_fp16.h>
#include <math.h>

#define NN    1025
#define CC    768
#define HH    12
#define HD    64
#define BH    96        // B*H
#define MROWS 8200      // B*N
#define NKV   1088      // 17*64  (kv padding)
#define NQP   1152      // 9*128  (q padding)

// ---------------- scratch (device globals, zero-initialized) ---------------
__device__ __half g_xh[MROWS * CC];       // x converted to fp16
__device__ __half g_wqh[3 * CC * CC];     // qkv_w fp16
__device__ __half g_wph[CC * CC];         // proj_w fp16
__device__ __half g_qh[BH * NQP * HD];    // fp16, pre-scaled by 1/8, padded rows = 0
__device__ __half g_kh[BH * NKV * HD];    // fp16, padded rows = 0
__device__ __half g_vth[BH * HD * NKV];   // V transposed [bh][d][j], fp16, padded = 0
__device__ __half g_aoh[MROWS * CC];      // attention output fp16, [B,N,C]
__device__ __align__(16) unsigned char g_bucket[NQP * NKV];
__device__ unsigned char g_lut[1923];     // bucket by r^2 = dy^2+dx^2

// ---------------- bucket LUT (fp64, 1923 entries) ---------------------------
__global__ void lut_kernel() {
    int r2 = blockIdx.x * 256 + threadIdx.x;
    if (r2 >= 1923) return;
    double dis = rint(sqrt((double)r2));
    int v;
    if (dis <= 1.9) {
        v = (int)dis;
    } else {
        double t = rint(1.9 + log(dis / 1.9) / log(8.0) * 1.9);
        if (t > 3.8) t = 3.8;
        v = (int)t;
    }
    g_lut[r2] = (unsigned char)v;
}

// ---------------- bucket fill (memory-bound, 4 cols per thread) -------------
__global__ void bucket_fill() {
    int idx = blockIdx.x * 256 + threadIdx.x;
    if (idx >= NQP * NKV / 4) return;
    int i = idx / (NKV / 4);
    int j4 = (idx - i * (NKV / 4)) * 4;
    uchar4 o;
    unsigned char* po = &o.x;
    if (i >= NN || i == 0) {
        unsigned char v = (i >= NN) ? 0 : 7;
        o.x = o.y = o.z = o.w = v;
    } else {
        int p = i - 1;
        int py = p >> 5, px = p & 31;
#pragma unroll
        for (int c = 0; c < 4; c++) {
            int j = j4 + c;
            unsigned char v;
            if (j >= NN) v = 0;
            else if (j == 0) v = 7;
            else {
                int q = j - 1;
                int dy = py - (q >> 5), dx = px - (q & 31);
                v = g_lut[dy * dy + dx * dx];
            }
            po[c] = v;
        }
    }
    *(uchar4*)(g_bucket + (size_t)i * NKV + j4) = o;
}

// ---------------- helpers ---------------------------------------------------
__device__ __forceinline__ void mma_f16(float* c, const unsigned* a, const unsigned* b) {
    asm volatile(
        "mma.sync.aligned.m16n8k16.row.col.f32.f16.f16.f32 "
        "{%0,%1,%2,%3}, {%4,%5,%6,%7}, {%8,%9}, {%0,%1,%2,%3};\n"
        : "+f"(c[0]), "+f"(c[1]), "+f"(c[2]), "+f"(c[3])
        : "r"(a[0]), "r"(a[1]), "r"(a[2]), "r"(a[3]), "r"(b[0]), "r"(b[1]));
}

__device__ __forceinline__ void ldsm4(unsigned* r, const void* p) {
    unsigned a = (unsigned)__cvta_generic_to_shared(p);
    asm volatile("ldmatrix.sync.aligned.m8n8.x4.shared.b16 {%0,%1,%2,%3}, [%4];"
                 : "=r"(r[0]), "=r"(r[1]), "=r"(r[2]), "=r"(r[3]) : "r"(a));
}

__device__ __forceinline__ unsigned pack_h2(float x, float y) {
    __half2 h = __floats2half2_rn(x, y);
    return *(unsigned*)&h;
}

__device__ __forceinline__ void cp16(void* dst, const void* src) {
    unsigned d = (unsigned)__cvta_generic_to_shared(dst);
    asm volatile("cp.async.cg.shared.global [%0], [%1], 16;" :: "r"(d), "l"(src));
}
#define CP_COMMIT() asm volatile("cp.async.commit_group;")
#define CP_WAIT1()  asm volatile("cp.async.wait_group 1;" ::: "memory")
#define CP_WAIT2()  asm volatile("cp.async.wait_group 2;" ::: "memory")
#define CP_WAIT3()  asm volatile("cp.async.wait_group 3;" ::: "memory")

// ---------------- fused fp32->fp16 conversion (one launch) ------------------
#define CVT_N1 ((size_t)MROWS * CC)
#define CVT_N2 (CVT_N1 + (size_t)3 * CC * CC)
#define CVT_N3 (CVT_N2 + (size_t)CC * CC)

__global__ void cvt_all(const float* __restrict__ x,
                        const float* __restrict__ wq,
                        const float* __restrict__ wp) {
    size_t i = ((size_t)blockIdx.x * 256 + threadIdx.x) * 4;
    if (i >= CVT_N3) return;
    const float* src; __half* dst; size_t off;
    if (i < CVT_N1)      { src = x;  dst = g_xh;  off = i; }
    else if (i < CVT_N2) { src = wq; dst = g_wqh; off = i - CVT_N1; }
    else                 { src = wp; dst = g_wph; off = i - CVT_N2; }
    float4 v = *(const float4*)(src + off);
    uint2 p;
    p.x = pack_h2(v.x, v.y);
    p.y = pack_h2(v.z, v.w);
    *(uint2*)(dst + off) = p;
}

// ---------------- dense GEMM core: fp16, cp.async 4-stage, ldmatrix ---------
#define TLD2 40
#define GNT  24
#define GEMM_SMEM (4 * 128 * TLD2 * 2 * 2)

#define ASM(S, R, C) gsm[(size_t)(S) * (128 * TLD2) + (R) * TLD2 + (C)]
#define BSM(S, R, C) gsm[4 * 128 * TLD2 + (size_t)(S) * (128 * TLD2) + (R) * TLD2 + (C)]

#define GEMM_LOAD(APTR, BPTR, S, K0)                                           \
    _Pragma("unroll") for (int c = 0; c < 2; c++) {                            \
        int ch = tid + c * 256;                                                \
        int row = ch >> 2, q = (ch & 3) * 8;                                   \
        int gm = m0 + row; if (gm >= MROWS) gm = MROWS - 1;                    \
        cp16(&ASM(S, row, q), APTR + (size_t)gm * CC + (K0) + q);              \
        cp16(&BSM(S, row, q), BPTR + (size_t)(n0 + row) * CC + (K0) + q);      \
    }

// ldmatrix row/col offsets per lane:
//   A tiles: row = (role&1)*8 + li8, col = (role>>1)*8
//   B tiles: row = (role>>1)*8 + li8, col = (role&1)*8
#define GEMM_F16_BODY(APTR, BPTR)                                              \
    extern __shared__ __half gsm[];                                            \
    int tid = threadIdx.x;                                                     \
    int lane = tid & 31, wid = tid >> 5;                                       \
    int wm = wid & 1, wn = wid >> 1;                                           \
    int g = lane >> 2, t = lane & 3;                                           \
    int role = lane >> 3, li8 = lane & 7;                                      \
    int arow = (role & 1) * 8 + li8, acol = (role >> 1) * 8;                   \
    int brow = (role >> 1) * 8 + li8, bcol = (role & 1) * 8;                   \
    int m0 = blockIdx.y * 128, n0 = blockIdx.x * 128;                          \
    float acc[4][4][4];                                                        \
    _Pragma("unroll") for (int mt = 0; mt < 4; mt++)                           \
    _Pragma("unroll") for (int nt = 0; nt < 4; nt++)                           \
    _Pragma("unroll") for (int i = 0; i < 4; i++) acc[mt][nt][i] = 0.f;        \
    GEMM_LOAD(APTR, BPTR, 0, 0)  CP_COMMIT();                                  \
    GEMM_LOAD(APTR, BPTR, 1, 32) CP_COMMIT();                                  \
    GEMM_LOAD(APTR, BPTR, 2, 64) CP_COMMIT();                                  \
    GEMM_LOAD(APTR, BPTR, 3, 96) CP_COMMIT();                                  \
    for (int it = 0; it < GNT; it++) {                                         \
        CP_WAIT3(); __syncthreads();                                           \
        int bi = it & 3;                                                       \
        _Pragma("unroll") for (int ks = 0; ks < 2; ks++) {                     \
            int kk = ks * 16;                                                  \
            unsigned af[4][4], bf[2][4];                                       \
            _Pragma("unroll") for (int mt = 0; mt < 4; mt++) {                 \
                int rb = wm * 64 + mt * 16;                                    \
                ldsm4(af[mt], &ASM(bi, rb + arow, kk + acol));                 \
            }                                                                  \
            _Pragma("unroll") for (int np = 0; np < 2; np++) {                 \
                int nb = wn * 32 + np * 16;                                    \
                ldsm4(bf[np], &BSM(bi, nb + brow, kk + bcol));                 \
            }                                                                  \
            _Pragma("unroll") for (int mt = 0; mt < 4; mt++)                   \
            _Pragma("unroll") for (int np = 0; np < 2; np++) {                 \
                mma_f16(acc[mt][np * 2],     af[mt], &bf[np][0]);              \
                mma_f16(acc[mt][np * 2 + 1], af[mt], &bf[np][2]);              \
            }                                                                  \
        }                                                                      \
        __syncthreads();                                                       \
        if (it + 4 < GNT) { GEMM_LOAD(APTR, BPTR, bi, (it + 4) * 32) }         \
        CP_COMMIT();                                                           \
    }

// ---------------- QKV GEMM ---------------------------------------------------
__global__ __launch_bounds__(256) void qkv_gemm_t() {
    const __half* Ap = g_xh;
    const __half* Bp = g_wqh;
    GEMM_F16_BODY(Ap, Bp)

#pragma unroll
    for (int mt = 0; mt < 4; mt++) {
#pragma unroll
        for (int half = 0; half < 2; half++) {
            int m = m0 + wm * 64 + mt * 16 + g + half * 8;
            if (m >= MROWS) continue;
            int b = m / NN, i = m - b * NN;
#pragma unroll
            for (int nt = 0; nt < 4; nt++) {
                int n = n0 + wn * 32 + nt * 8 + 2 * t;
                int which = n / CC;
                int cc = n - which * CC;
                int h = cc >> 6, d = cc & 63;
                int bhv = b * HH + h;
                float vx = acc[mt][nt][half * 2 + 0];
                float vy = acc[mt][nt][half * 2 + 1];
                if (which == 0) {
                    unsigned p = pack_h2(vx * 0.125f, vy * 0.125f);
                    *(unsigned*)(g_qh + ((size_t)bhv * NQP + i) * HD + d) = p;
                } else if (which == 1) {
                    unsigned p = pack_h2(vx, vy);
                    *(unsigned*)(g_kh + ((size_t)bhv * NKV + i) * HD + d) = p;
                } else {
                    size_t base = (size_t)bhv * HD;
                    g_vth[(base + d) * NKV + i]     = __float2half_rn(vx);
                    g_vth[(base + d + 1) * NKV + i] = __float2half_rn(vy);
                }
            }
        }
    }
}

// ---------------- proj GEMM --------------------------------------------------
__global__ __launch_bounds__(256) void proj_gemm_t(const float* __restrict__ bias,
                                                   float* __restrict__ out) {
    const __half* Ap = g_aoh;
    const __half* Bp = g_wph;
    GEMM_F16_BODY(Ap, Bp)

#pragma unroll
    for (int mt = 0; mt < 4; mt++) {
#pragma unroll
        for (int half = 0; half < 2; half++) {
            int m = m0 + wm * 64 + mt * 16 + g + half * 8;
            if (m >= MROWS) continue;
#pragma unroll
            for (int nt = 0; nt < 4; nt++) {
                int n = n0 + wn * 32 + nt * 8 + 2 * t;
                float2 v;
                v.x = acc[mt][nt][half * 2 + 0] + bias[n];
                v.y = acc[mt][nt][half * 2 + 1] + bias[n + 1];
                *(float2*)(out + (size_t)m * CC + n) = v;
            }
        }
    }
}

// ---------------- flash attention: 256 threads, 8 warps, ldmatrix -----------
#define QLD2 72
#define KVSZ (64 * QLD2)
#define HOF_K (128 * QLD2)
#define HOF_V (HOF_K + 2 * KVSZ)
#define HOF_P (HOF_V + 2 * KVSZ)
#define HOF_LK (HOF_P + 128 * QLD2)
#define HOF_BK (HOF_LK + 2048)
#define BKSTR 80
#define BKSZ  (128 * BKSTR)
#define FLASH_SMEM (HOF_BK * 2 + 2 * BKSZ)

#define FKV_LOAD(S, KT)                                                          \
    { int jj0 = (KT) * 64;                                                       \
      _Pragma("unroll") for (int c = 0; c < 2; c++) {                            \
          int ch = tid + c * 256;                                                \
          int r = ch >> 3, q = (ch & 7) * 8;                                     \
          cp16(Ks + (S) * KVSZ + r * QLD2 + q, kb + (size_t)(jj0 + r) * HD + q); \
          cp16(Vs + (S) * KVSZ + r * QLD2 + q, vtb + (size_t)r * NKV + jj0 + q); \
      }                                                                          \
      _Pragma("unroll") for (int c = 0; c < 2; c++) {                            \
          int ch = tid + c * 256;                                                \
          int r = ch >> 2, q = (ch & 3) * 16;                                    \
          cp16(Bkt + (S) * BKSZ + r * BKSTR + q,                                 \
               g_bucket + (size_t)(i0 + r) * NKV + jj0 + q);                     \
      } }

__global__ void __launch_bounds__(256, 2) flash_mma(const float* __restrict__ rpe_w) {
    extern __shared__ __half smh[];
    __half* Qs = smh;
    __half* Ks = smh + HOF_K;
    __half* Vs = smh + HOF_V;
    __half* Ps = smh + HOF_P;
    float*  Lk = (float*)(smh + HOF_LK);
    unsigned char* Bkt = (unsigned char*)(smh + HOF_BK);

    int tid = threadIdx.x;
    int lane = tid & 31, w = tid >> 5;
    int g = lane >> 2, t = lane & 3;
    int role = lane >> 3, li8 = lane & 7;
    int arow = (role & 1) * 8 + li8, acol = (role >> 1) * 8;   // A-operand lds
    int brow = (role >> 1) * 8 + li8, bcol = (role & 1) * 8;   // B-operand lds
    int bh = blockIdx.x;
    int b = bh / HH, h = bh - b * HH;
    int i0 = blockIdx.y * 128;

    const __half* qb  = g_qh  + (size_t)bh * NQP * HD;
    const __half* kb  = g_kh  + (size_t)bh * NKV * HD;
    const __half* vtb = g_vth + (size_t)bh * HD * NKV;

    // prefetch Q (own group), then KV+bucket tiles 0 and 1
#pragma unroll
    for (int c = 0; c < 4; c++) {
        int ch = tid + c * 256;
        int r = ch >> 3, q = (ch & 7) * 8;
        cp16(Qs + r * QLD2 + q, qb + (size_t)(i0 + r) * HD + q);
    }
    CP_COMMIT();
    FKV_LOAD(0, 0) CP_COMMIT();
    FKV_LOAD(1, 1) CP_COMMIT();

    CP_WAIT2(); __syncthreads();   // Q ready

    // per-row RPE lookup table
    for (int tq = tid; tq < 1024; tq += 256) {
        int r = tq >> 3, m = tq & 7;
        float s = 0.f;
#pragma unroll
        for (int d = 0; d < HD; d++)
            s += __half2float(Qs[r * QLD2 + d]) * rpe_w[d * 8 + m];
        Lk[r * 8 + m] = s;
    }
    __syncthreads();

    int rl = w * 16 + g;
    int rbq = w * 16;                          // warp's m-tile base row
    int grow[2] = { i0 + rl, i0 + rl + 8 };

    float mx[2] = { -1e30f, -1e30f }, ll[2] = { 0.f, 0.f };
    float oacc[8][4];
#pragma unroll
    for (int nt = 0; nt < 8; nt++)
#pragma unroll
        for (int c = 0; c < 4; c++) oacc[nt][c] = 0.f;

    for (int kt = 0; kt < 17; kt++) {
        int j0 = kt * 64;
        CP_WAIT1(); __syncthreads();
        int bi = kt & 1;
        const __half* Kb = Ks + bi * KVSZ;
        const __half* Vb = Vs + bi * KVSZ;
        const unsigned char* Bk = Bkt + bi * BKSZ;

        // S = Q K^T (ldmatrix fragments)
        float sacc[8][4];
#pragma unroll
        for (int nt = 0; nt < 8; nt++)
#pragma unroll
            for (int c = 0; c < 4; c++) sacc[nt][c] = 0.f;
#pragma unroll
        for (int ks = 0; ks < 4; ks++) {
            int kk = ks * 16;
            unsigned a0[4];
            ldsm4(a0, &Qs[(rbq + arow) * QLD2 + kk + acol]);
#pragma unroll
            for (int np = 0; np < 4; np++) {
                unsigned bf[4];
                ldsm4(bf, &Kb[(np * 16 + brow) * QLD2 + kk + bcol]);
                mma_f16(sacc[np * 2],     a0, &bf[0]);
                mma_f16(sacc[np * 2 + 1], a0, &bf[2]);
            }
        }

        // RPE bias gather (bucket from smem) + j-mask
        {
            int r_lo = rl, r_hi = rl + 8;
#pragma unroll
            for (int nt = 0; nt < 8; nt++) {
                int jo = nt * 8 + 2 * t;
                int j = j0 + jo;
                unsigned short b_lo = *(const unsigned short*)&Bk[r_lo * BKSTR + jo];
                unsigned short b_hi = *(const unsigned short*)&Bk[r_hi * BKSTR + jo];
                if (j < NN) {
                    sacc[nt][0] += Lk[r_lo * 8 + (b_lo & 0xFF)];
                    sacc[nt][2] += Lk[r_hi * 8 + (b_hi & 0xFF)];
                } else { sacc[nt][0] = -1e30f; sacc[nt][2] = -1e30f; }
                if (j + 1 < NN) {
                    sacc[nt][1] += Lk[r_lo * 8 + (b_lo >> 8)];
                    sacc[nt][3] += Lk[r_hi * 8 + (b_hi >> 8)];
                } else { sacc[nt][1] = -1e30f; sacc[nt][3] = -1e30f; }
            }
        }

        // online softmax (quad-owned rows; shfl xor 1,2)
#pragma unroll
        for (int s = 0; s < 2; s++) {
            int c0 = s * 2, c1 = c0 + 1;
            float mtv = -1e30f;
#pragma unroll
            for (int nt = 0; nt < 8; nt++)
                mtv = fmaxf(mtv, fmaxf(sacc[nt][c0], sacc[nt][c1]));
            mtv = fmaxf(mtv, __shfl_xor_sync(0xffffffffu, mtv, 1));
            mtv = fmaxf(mtv, __shfl_xor_sync(0xffffffffu, mtv, 2));
            float mn = fmaxf(mx[s], mtv);
            float al = __expf(mx[s] - mn);
            float sum = 0.f;
            int prow = rl + s * 8;
#pragma unroll
            for (int nt = 0; nt < 8; nt++) {
                float p0 = __expf(sacc[nt][c0] - mn);
                float p1 = __expf(sacc[nt][c1] - mn);
                sum += p0 + p1;
                *(unsigned*)(Ps + prow * QLD2 + nt * 8 + 2 * t) = pack_h2(p0, p1);
            }
            sum += __shfl_xor_sync(0xffffffffu, sum, 1);
            sum += __shfl_xor_sync(0xffffffffu, sum, 2);
            ll[s] = ll[s] * al + sum;
            mx[s] = mn;
#pragma unroll
            for (int nt = 0; nt < 8; nt++) {
                oacc[nt][c0] *= al;
                oacc[nt][c1] *= al;
            }
        }
        __syncwarp();   // P rows are warp-local

        // O += P V (ldmatrix fragments)
#pragma unroll
        for (int ks = 0; ks < 4; ks++) {
            int kk = ks * 16;
            unsigned a0[4];
            ldsm4(a0, &Ps[(rbq + arow) * QLD2 + kk + acol]);
#pragma unroll
            for (int np = 0; np < 4; np++) {
                unsigned bf[4];
                ldsm4(bf, &Vb[(np * 16 + brow) * QLD2 + kk + bcol]);
                mma_f16(oacc[np * 2],     a0, &bf[0]);
                mma_f16(oacc[np * 2 + 1], a0, &bf[2]);
            }
        }
        __syncthreads();
        if (kt + 2 < 17) { FKV_LOAD(bi, kt + 2) }
        CP_COMMIT();
    }

    // normalize + store (fp16 — proj consumes half)
#pragma unroll
    for (int s = 0; s < 2; s++) {
        int gr = grow[s];
        if (gr < NN) {
            float inv = 1.0f / ll[s];
            int c0 = s * 2;
#pragma unroll
            for (int nt = 0; nt < 8; nt++) {
                unsigned p = pack_h2(oacc[nt][c0] * inv, oacc[nt][c0 + 1] * inv);
                *(unsigned*)(g_aoh + ((size_t)b * NN + gr) * CC + h * HD + nt * 8 + 2 * t) = p;
            }
        }
    }
}

// ---------------- launch ----------------------------------------------------
extern "C" void kernel_launch(void* const* d_in, const int* in_sizes, int n_in,
                              void* d_out, int out_size) {
    (void)in_sizes; (void)n_in; (void)out_size;
    const float* x      = (const float*)d_in[0];
    const float* qkv_w  = (const float*)d_in[1];
    const float* proj_w = (const float*)d_in[2];
    const float* proj_b = (const float*)d_in[3];
    const float* rpe_w  = (const float*)d_in[4];
    float* out = (float*)d_out;

    cudaFuncSetAttribute(flash_mma,
                         cudaFuncAttributeMaxDynamicSharedMemorySize, FLASH_SMEM);
    cudaFuncSetAttribute(qkv_gemm_t,
                         cudaFuncAttributeMaxDynamicSharedMemorySize, GEMM_SMEM);
    cudaFuncSetAttribute(proj_gemm_t,
                         cudaFuncAttributeMaxDynamicSharedMemorySize, GEMM_SMEM);

    lut_kernel<<<8, 256>>>();
    bucket_fill<<<(NQP * NKV / 4 + 255) / 256, 256>>>();
    cvt_all<<<(unsigned)((CVT_N3 / 4 + 255) / 256), 256>>>(x, qkv_w, proj_w);

    qkv_gemm_t<<<dim3(2304 / 128, (MROWS + 127) / 128), 256, GEMM_SMEM>>>();
    flash_mma<<<dim3(BH, NQP / 128), 256, FLASH_SMEM>>>(rpe_w);
    proj_gemm_t<<<dim3(CC / 128, (MROWS + 127) / 128), 256, GEMM_SMEM>>>(proj_b, out);
}